// round 12
// baseline (speedup 1.0000x reference)
#include <cuda_runtime.h>
#include <cuda_bf16.h>
#include <math.h>
#include <stdint.h>

#define BB 2
#define TT 2048
#define DD 1024
#define LL 4
#define VV 32000
#define FF (4*DD)
#define NROWS (BB*TT)   // 4096

// WT scratch layout (elements): per layer: WqT,WkT,WvT (DD*DD each), w1T (DD*FF), w2T (FF*DD)
#define LYR_BLK (3*DD*DD + DD*FF + FF*DD)
#define PROJ_OFF ((size_t)LL*LYR_BLK)
#define WT_TOTAL (PROJ_OFF + (size_t)DD*VV)

// ---------------- scratch (device globals; no allocations allowed) ----------
__device__ float g_X[(size_t)NROWS*DD];
__device__ float g_Hf[(size_t)NROWS*DD];
__device__ float g_QKVf[(size_t)3*NROWS*DD];
__device__ float g_S[(size_t)BB*TT*TT];
__device__ __nv_bfloat16 g_Hh[(size_t)NROWS*DD],   g_Hl[(size_t)NROWS*DD];
__device__ __nv_bfloat16 g_Xh[(size_t)NROWS*DD],   g_Xl[(size_t)NROWS*DD];
__device__ __nv_bfloat16 g_QKVh[(size_t)3*NROWS*DD], g_QKVl[(size_t)3*NROWS*DD];
__device__ __nv_bfloat16 g_Sh[(size_t)BB*TT*TT],   g_Sl[(size_t)BB*TT*TT];
__device__ __nv_bfloat16 g_Fh[(size_t)NROWS*FF],   g_Fl[(size_t)NROWS*FF];
__device__ __nv_bfloat16 g_WTh[WT_TOTAL],          g_WTl[WT_TOTAL];
__device__ __nv_bfloat16 g_VTh[(size_t)BB*DD*TT],  g_VTl[(size_t)BB*DD*TT];

// ============================ helpers ========================================
__device__ __forceinline__ uint32_t smem_u32(const void* p) {
    uint32_t a;
    asm("{ .reg .u64 t; cvta.to.shared.u64 t, %1; cvt.u32.u64 %0, t; }" : "=r"(a) : "l"(p));
    return a;
}
// 64B-row swizzle: XOR byte bits [4:6) with bits [7:9)
#define SWZ64(o) ((o) ^ (((o) >> 3) & 0x30))

__device__ __forceinline__ void ldm_x4(uint32_t* r, uint32_t addr) {
    asm volatile("ldmatrix.sync.aligned.m8n8.x4.shared.b16 {%0,%1,%2,%3}, [%4];"
                 : "=r"(r[0]), "=r"(r[1]), "=r"(r[2]), "=r"(r[3]) : "r"(addr));
}
__device__ __forceinline__ void mma_bf16(float* d, const uint32_t* a, uint32_t b0, uint32_t b1) {
    asm volatile(
        "mma.sync.aligned.m16n8k16.row.col.f32.bf16.bf16.f32 "
        "{%0,%1,%2,%3}, {%4,%5,%6,%7}, {%8,%9}, {%0,%1,%2,%3};"
        : "+f"(d[0]), "+f"(d[1]), "+f"(d[2]), "+f"(d[3])
        : "r"(a[0]), "r"(a[1]), "r"(a[2]), "r"(a[3]), "r"(b0), "r"(b1));
}
__device__ __forceinline__ void cpa16(uint32_t dst, const void* src) {
    asm volatile("cp.async.cg.shared.global [%0], [%1], 16;" :: "r"(dst), "l"(src));
}
#define CP_COMMIT() asm volatile("cp.async.commit_group;" ::: "memory")
#define CP_WAIT2()  asm volatile("cp.async.wait_group 2;" ::: "memory")

__device__ __forceinline__ uint32_t pk2(__nv_bfloat16 a, __nv_bfloat16 b) {
    __nv_bfloat162 t = __halves2bfloat162(a, b);
    return *reinterpret_cast<uint32_t*>(&t);
}

// SMEM stage (32 KB): Ah @0, Al @8192, Bh @16384, Bl @24576. 128 rows x 32 bf16.
#define STG_SZ 32768
#define NSTG 4
#define SHM_TOTAL (NSTG*STG_SZ)   // 128 KB
#define BK 32

// ---------------- all-bf16 split GEMM --------------------------------------
// C = alpha * (Ah+Al) @ (Bh+Bl)^T  (+bias)(+relu)(+addm), 3-term split MMA.
// A: [M][K] bf16 hi/lo. B: [N][K] bf16 hi/lo.
// Out: fp32 Cf if (cfMask>>z)&1; split Ch/Cl if (chMask>>z)&1.
// cmode: 0 none, 1 = causal tile-skip (QK^T), 3 = causal K-limit + balanced
// fold (A=S case): grid.y halved, each CTA does row-tiles y and (2*gridDim.y-1-y).
__global__ __launch_bounds__(256) void gemm_k(
    const __nv_bfloat16* __restrict__ Ahp, const __nv_bfloat16* __restrict__ Alp,
    const __nv_bfloat16* __restrict__ Bhp, const __nv_bfloat16* __restrict__ Blp,
    float* __restrict__ Cf,
    __nv_bfloat16* __restrict__ Ch, __nv_bfloat16* __restrict__ Cl,
    int M, int N, int K, float alpha,
    const float* __restrict__ bias,
    const float* __restrict__ addm,
    int relu, int cmode, int cfMask, int chMask,
    long sA, long sB, long sC, long sAdd)
{
    extern __shared__ char smem[];
    const uint32_t smb = smem_u32(smem);
    const int tid = threadIdx.x;
    const long z = blockIdx.z;

    Ahp += z * sA; Alp += z * sA;
    Bhp += z * sB; Blp += z * sB;
    const bool wCf = Cf && ((cfMask >> z) & 1);
    const bool wCh = Ch && ((chMask >> z) & 1);
    if (Cf) Cf += z * sC;
    if (Ch) { Ch += z * sC; Cl += z * sC; }
    if (addm) addm += z * sAdd;

    const int colBlk = blockIdx.x * 128;
    const int lr = tid >> 1, half = tid & 1;
    const uint32_t o0 = SWZ64((uint32_t)(lr * 64 + half * 32));
    const uint32_t o1 = SWZ64((uint32_t)(lr * 64 + half * 32 + 16));
    const __nv_bfloat16* pb_h = Bhp + (long)(colBlk + lr) * K + half * 16;
    const __nv_bfloat16* pb_l = Blp + (long)(colBlk + lr) * K + half * 16;

    const int w = tid >> 5, lane = tid & 31;
    const int wm = (w & 1) * 64;
    const int wn = (w >> 1) * 32;

    const int nRep = (cmode == 3) ? 2 : 1;
    for (int rep = 0; rep < nRep; rep++) {
        int rowBlk;
        if (cmode == 3)
            rowBlk = (rep ? ((int)gridDim.y * 2 - 1 - (int)blockIdx.y)
                          : (int)blockIdx.y) * 128;
        else
            rowBlk = blockIdx.y * 128;
        if (cmode == 1 && colBlk >= rowBlk + 128) continue;

        int kMax = K;
        if (cmode == 3) { kMax = rowBlk + 128; if (kMax > K) kMax = K; }
        const int nCh = kMax / BK;

        const __nv_bfloat16* pa_h = Ahp + (long)(rowBlk + lr) * K + half * 16;
        const __nv_bfloat16* pa_l = Alp + (long)(rowBlk + lr) * K + half * 16;

        if (rep > 0) __syncthreads();   // stage reuse across reps

        // prologue: issue first NSTG-1 = 3 chunks
#pragma unroll
        for (int s = 0; s < NSTG - 1; s++) {
            if (s < nCh) {
                uint32_t sb = smb + (uint32_t)s * STG_SZ;
                long k0 = (long)s * BK;
                cpa16(sb + o0,         pa_h + k0);  cpa16(sb + o1,         pa_h + k0 + 8);
                cpa16(sb + 8192  + o0, pa_l + k0);  cpa16(sb + 8192  + o1, pa_l + k0 + 8);
                cpa16(sb + 16384 + o0, pb_h + k0);  cpa16(sb + 16384 + o1, pb_h + k0 + 8);
                cpa16(sb + 24576 + o0, pb_l + k0);  cpa16(sb + 24576 + o1, pb_l + k0 + 8);
            }
            CP_COMMIT();
        }

        float acc[4][4][4];
#pragma unroll
        for (int i = 0; i < 4; i++)
#pragma unroll
            for (int j = 0; j < 4; j++)
#pragma unroll
                for (int k = 0; k < 4; k++) acc[i][j][k] = 0.f;

        int st_c = 0;
        int st_n = NSTG - 1;
        for (int c = 0; c < nCh; c++) {
            CP_WAIT2();
            __syncthreads();
            // issue chunk c+3 into stage st_n (its readers passed the barrier)
            if (c + NSTG - 1 < nCh) {
                uint32_t sbn = smb + (uint32_t)st_n * STG_SZ;
                long k0 = (long)(c + NSTG - 1) * BK;
                cpa16(sbn + o0,         pa_h + k0);  cpa16(sbn + o1,         pa_h + k0 + 8);
                cpa16(sbn + 8192  + o0, pa_l + k0);  cpa16(sbn + 8192  + o1, pa_l + k0 + 8);
                cpa16(sbn + 16384 + o0, pb_h + k0);  cpa16(sbn + 16384 + o1, pb_h + k0 + 8);
                cpa16(sbn + 24576 + o0, pb_l + k0);  cpa16(sbn + 24576 + o1, pb_l + k0 + 8);
            }
            CP_COMMIT();

            const uint32_t sb = smb + (uint32_t)st_c * STG_SZ;
#pragma unroll
            for (int ks = 0; ks < 2; ks++) {
                uint32_t bh[4][2], bl[4][2];
#pragma unroll
                for (int nt2 = 0; nt2 < 2; nt2++) {
                    uint32_t off = SWZ64((uint32_t)((wn + nt2 * 16 + ((lane >> 4) & 1) * 8 + (lane & 7)) * 64
                                                    + ks * 32 + ((lane >> 3) & 1) * 16));
                    uint32_t r[4];
                    ldm_x4(r, sb + 16384 + off);
                    bh[nt2 * 2][0] = r[0]; bh[nt2 * 2][1] = r[1];
                    bh[nt2 * 2 + 1][0] = r[2]; bh[nt2 * 2 + 1][1] = r[3];
                    ldm_x4(r, sb + 24576 + off);
                    bl[nt2 * 2][0] = r[0]; bl[nt2 * 2][1] = r[1];
                    bl[nt2 * 2 + 1][0] = r[2]; bl[nt2 * 2 + 1][1] = r[3];
                }
#pragma unroll
                for (int mt = 0; mt < 4; mt++) {
                    uint32_t off = SWZ64((uint32_t)((wm + mt * 16 + (lane & 15)) * 64
                                                    + ks * 32 + (lane >> 4) * 16));
                    uint32_t ah4[4], al4[4];
                    ldm_x4(ah4, sb + off);
                    ldm_x4(al4, sb + 8192 + off);
#pragma unroll
                    for (int nt = 0; nt < 4; nt++) mma_bf16(acc[mt][nt], ah4, bh[nt][0], bh[nt][1]);
#pragma unroll
                    for (int nt = 0; nt < 4; nt++) mma_bf16(acc[mt][nt], ah4, bl[nt][0], bl[nt][1]);
#pragma unroll
                    for (int nt = 0; nt < 4; nt++) mma_bf16(acc[mt][nt], al4, bh[nt][0], bh[nt][1]);
                }
            }
            st_c = (st_c + 1 == NSTG) ? 0 : st_c + 1;
            st_n = (st_n + 1 == NSTG) ? 0 : st_n + 1;
        }

        // ---- epilogue ----
#pragma unroll
        for (int mt = 0; mt < 4; mt++) {
            int r0 = rowBlk + wm + mt * 16 + (lane >> 2);
#pragma unroll
            for (int nt = 0; nt < 4; nt++) {
                int cc = colBlk + wn + nt * 8 + (lane & 3) * 2;
                float2 v0, v1;
                v0.x = acc[mt][nt][0] * alpha; v0.y = acc[mt][nt][1] * alpha;
                v1.x = acc[mt][nt][2] * alpha; v1.y = acc[mt][nt][3] * alpha;
                if (bias) {
                    float2 bb = *reinterpret_cast<const float2*>(bias + cc);
                    v0.x += bb.x; v0.y += bb.y; v1.x += bb.x; v1.y += bb.y;
                }
                if (relu) {
                    v0.x = fmaxf(v0.x, 0.f); v0.y = fmaxf(v0.y, 0.f);
                    v1.x = fmaxf(v1.x, 0.f); v1.y = fmaxf(v1.y, 0.f);
                }
                if (addm) {
                    float2 a0 = *reinterpret_cast<const float2*>(addm + (long)r0 * N + cc);
                    float2 a1 = *reinterpret_cast<const float2*>(addm + (long)(r0 + 8) * N + cc);
                    v0.x += a0.x; v0.y += a0.y; v1.x += a1.x; v1.y += a1.y;
                }
                if (wCf) {
                    *reinterpret_cast<float2*>(Cf + (long)r0 * N + cc) = v0;
                    *reinterpret_cast<float2*>(Cf + (long)(r0 + 8) * N + cc) = v1;
                }
                if (wCh) {
                    __nv_bfloat16 h0 = __float2bfloat16(v0.x), h1 = __float2bfloat16(v0.y);
                    __nv_bfloat16 h2 = __float2bfloat16(v1.x), h3 = __float2bfloat16(v1.y);
                    *reinterpret_cast<uint32_t*>(Ch + (long)r0 * N + cc)       = pk2(h0, h1);
                    *reinterpret_cast<uint32_t*>(Ch + (long)(r0 + 8) * N + cc) = pk2(h2, h3);
                    *reinterpret_cast<uint32_t*>(Cl + (long)r0 * N + cc) =
                        pk2(__float2bfloat16(v0.x - __bfloat162float(h0)),
                            __float2bfloat16(v0.y - __bfloat162float(h1)));
                    *reinterpret_cast<uint32_t*>(Cl + (long)(r0 + 8) * N + cc) =
                        pk2(__float2bfloat16(v1.x - __bfloat162float(h2)),
                            __float2bfloat16(v1.y - __bfloat162float(h3)));
                }
            }
        }
    }
}

// ---------------- transpose + bf16 split: W[R][C] -> T[C][R] hi/lo ----------
__global__ void tsplit_k(const float* __restrict__ W,
                         __nv_bfloat16* __restrict__ Th, __nv_bfloat16* __restrict__ Tl,
                         int R, int C, long sIn, long sOut)
{
    __shared__ float t[32][33];
    W  += (long)blockIdx.z * sIn;
    Th += (long)blockIdx.z * sOut;
    Tl += (long)blockIdx.z * sOut;
    int c0 = blockIdx.x * 32, r0 = blockIdx.y * 32;
    int tx = threadIdx.x, ty = threadIdx.y;
#pragma unroll
    for (int j = 0; j < 32; j += 8)
        t[ty + j][tx] = W[(long)(r0 + ty + j) * C + c0 + tx];
    __syncthreads();
#pragma unroll
    for (int j = 0; j < 32; j += 8) {
        int oc = c0 + ty + j;
        float v = t[tx][ty + j];
        __nv_bfloat16 h = __float2bfloat16(v);
        float lo = v - __bfloat162float(h);
        Th[(long)oc * R + r0 + tx] = h;
        Tl[(long)oc * R + r0 + tx] = __float2bfloat16(lo);
    }
}

// ---------------- embed: x = emb[tok] + pos ---------------------------------
__global__ void embed_k(const int* __restrict__ tok,
                        const float* __restrict__ emb,
                        const float* __restrict__ pos,
                        float* __restrict__ X)
{
    int idx = blockIdx.x * blockDim.x + threadIdx.x;
    int total = NROWS * (DD / 4);
    if (idx >= total) return;
    int d4 = idx % (DD / 4);
    int bt = idx / (DD / 4);
    int t = bt % TT;
    int token = tok[bt];
    float4 e = reinterpret_cast<const float4*>(emb + (size_t)token * DD)[d4];
    float4 p = reinterpret_cast<const float4*>(pos + (size_t)t * DD)[d4];
    float4 o; o.x = e.x + p.x; o.y = e.y + p.y; o.z = e.z + p.z; o.w = e.w + p.w;
    reinterpret_cast<float4*>(X + (size_t)bt * DD)[d4] = o;
}

// ---------------- layernorm: fp32 in -> (opt fp32) + bf16-split out ---------
__global__ void ln_k(const float* __restrict__ X,
                     float* __restrict__ Yf,
                     __nv_bfloat16* __restrict__ Yh, __nv_bfloat16* __restrict__ Yl,
                     const float* __restrict__ g, const float* __restrict__ b,
                     int writeF)
{
    int row = blockIdx.x;
    int tid = threadIdx.x;
    const float4* x4 = reinterpret_cast<const float4*>(X + (size_t)row * DD);
    float4 v = x4[tid];
    __shared__ float sh[256];

    float s = v.x + v.y + v.z + v.w;
    sh[tid] = s; __syncthreads();
    for (int o = 128; o > 0; o >>= 1) { if (tid < o) sh[tid] += sh[tid + o]; __syncthreads(); }
    float mu = sh[0] * (1.0f / DD);
    __syncthreads();

    float c0 = v.x - mu, c1 = v.y - mu, c2 = v.z - mu, c3 = v.w - mu;
    sh[tid] = c0 * c0 + c1 * c1 + c2 * c2 + c3 * c3; __syncthreads();
    for (int o = 128; o > 0; o >>= 1) { if (tid < o) sh[tid] += sh[tid + o]; __syncthreads(); }
    float inv = rsqrtf(sh[0] * (1.0f / DD) + 1e-5f);

    float4 gv = reinterpret_cast<const float4*>(g)[tid];
    float4 bv = reinterpret_cast<const float4*>(b)[tid];
    float4 o4;
    o4.x = c0 * inv * gv.x + bv.x;
    o4.y = c1 * inv * gv.y + bv.y;
    o4.z = c2 * inv * gv.z + bv.z;
    o4.w = c3 * inv * gv.w + bv.w;
    if (writeF)
        reinterpret_cast<float4*>(Yf + (size_t)row * DD)[tid] = o4;

    __nv_bfloat16 h0 = __float2bfloat16(o4.x), h1 = __float2bfloat16(o4.y);
    __nv_bfloat16 h2 = __float2bfloat16(o4.z), h3 = __float2bfloat16(o4.w);
    uint2 hv, lv;
    hv.x = pk2(h0, h1); hv.y = pk2(h2, h3);
    lv.x = pk2(__float2bfloat16(o4.x - __bfloat162float(h0)),
               __float2bfloat16(o4.y - __bfloat162float(h1)));
    lv.y = pk2(__float2bfloat16(o4.z - __bfloat162float(h2)),
               __float2bfloat16(o4.w - __bfloat162float(h3)));
    *reinterpret_cast<uint2*>(Yh + (size_t)row * DD + tid * 4) = hv;
    *reinterpret_cast<uint2*>(Yl + (size_t)row * DD + tid * 4) = lv;
}

// ---------------- causal softmax: fp32 S -> bf16-split out ------------------
__global__ void softmax_k(const float* __restrict__ S,
                          __nv_bfloat16* __restrict__ Sh, __nv_bfloat16* __restrict__ Sl)
{
    int t = blockIdx.x, b = blockIdx.y;
    int tid = threadIdx.x;
    const float* row = S + ((size_t)b * TT + t) * TT;
    __nv_bfloat16* rh = Sh + ((size_t)b * TT + t) * TT;
    __nv_bfloat16* rl = Sl + ((size_t)b * TT + t) * TT;
    __shared__ float ex[TT];
    __shared__ float sh[256];

    float mx = -1e30f;
    for (int c = tid; c <= t; c += 256) { float v = row[c]; ex[c] = v; mx = fmaxf(mx, v); }
    sh[tid] = mx; __syncthreads();
    for (int o = 128; o > 0; o >>= 1) { if (tid < o) sh[tid] = fmaxf(sh[tid], sh[tid + o]); __syncthreads(); }
    mx = sh[0]; __syncthreads();

    float sum = 0.f;
    for (int c = tid; c <= t; c += 256) { float e = __expf(ex[c] - mx); ex[c] = e; sum += e; }
    sh[tid] = sum; __syncthreads();
    for (int o = 128; o > 0; o >>= 1) { if (tid < o) sh[tid] += sh[tid + o]; __syncthreads(); }
    float inv = 1.0f / sh[0];

    for (int c = tid; c < TT; c += 256) {
        float p = (c <= t) ? ex[c] * inv : 0.0f;
        __nv_bfloat16 h = __float2bfloat16(p);
        rh[c] = h;
        rl[c] = __float2bfloat16(p - __bfloat162float(h));
    }
}

// ---------------- host-side dispatch -----------------------------------------
static void gemm(const __nv_bfloat16* Ah, const __nv_bfloat16* Al,
                 const __nv_bfloat16* Bh, const __nv_bfloat16* Bl,
                 float* Cf, __nv_bfloat16* Ch, __nv_bfloat16* Cl,
                 int M, int N, int K, float alpha,
                 const float* bias, const float* addm, int relu, int cmode,
                 int cfMask, int chMask, int batch, int gy,
                 long sA, long sB, long sC, long sAdd)
{
    dim3 grid(N / 128, gy, batch), blk(256);
    gemm_k<<<grid, blk, SHM_TOTAL>>>(Ah, Al, Bh, Bl, Cf, Ch, Cl,
                                     M, N, K, alpha, bias, addm, relu, cmode,
                                     cfMask, chMask, sA, sB, sC, sAdd);
}

static void tsplit(const float* W, __nv_bfloat16* Th, __nv_bfloat16* Tl,
                   int R, int C, int batch, long sIn, long sOut)
{
    dim3 g(C / 32, R / 32, batch), b(32, 8);
    tsplit_k<<<g, b>>>(W, Th, Tl, R, C, sIn, sOut);
}

extern "C" void kernel_launch(void* const* d_in, const int* in_sizes, int n_in,
                              void* d_out, int out_size)
{
    const int*   tokens = (const int*)  d_in[0];
    const float* emb    = (const float*)d_in[1];
    const float* pos    = (const float*)d_in[2];
    const float* Wq     = (const float*)d_in[3];
    const float* Wk     = (const float*)d_in[4];
    const float* Wv     = (const float*)d_in[5];
    const float* w1     = (const float*)d_in[6];
    const float* b1     = (const float*)d_in[7];
    const float* w2     = (const float*)d_in[8];
    const float* b2     = (const float*)d_in[9];
    const float* g1     = (const float*)d_in[10];
    const float* bln1   = (const float*)d_in[11];
    const float* g2     = (const float*)d_in[12];
    const float* bln2   = (const float*)d_in[13];
    const float* projw  = (const float*)d_in[14];
    const float* projb  = (const float*)d_in[15];
    float* out = (float*)d_out;

    cudaFuncSetAttribute(gemm_k, cudaFuncAttributeMaxDynamicSharedMemorySize, SHM_TOTAL);

    float *X, *Hf, *QKVf, *S;
    __nv_bfloat16 *Hh, *Hl, *Xh, *Xl, *QKVh, *QKVl, *Sh, *Sl, *Fh, *Fl, *WTh, *WTl, *VTh, *VTl;
    cudaGetSymbolAddress((void**)&X,    g_X);
    cudaGetSymbolAddress((void**)&Hf,   g_Hf);
    cudaGetSymbolAddress((void**)&QKVf, g_QKVf);
    cudaGetSymbolAddress((void**)&S,    g_S);
    cudaGetSymbolAddress((void**)&Hh,   g_Hh);   cudaGetSymbolAddress((void**)&Hl,   g_Hl);
    cudaGetSymbolAddress((void**)&Xh,   g_Xh);   cudaGetSymbolAddress((void**)&Xl,   g_Xl);
    cudaGetSymbolAddress((void**)&QKVh, g_QKVh); cudaGetSymbolAddress((void**)&QKVl, g_QKVl);
    cudaGetSymbolAddress((void**)&Sh,   g_Sh);   cudaGetSymbolAddress((void**)&Sl,   g_Sl);
    cudaGetSymbolAddress((void**)&Fh,   g_Fh);   cudaGetSymbolAddress((void**)&Fl,   g_Fl);
    cudaGetSymbolAddress((void**)&WTh,  g_WTh);  cudaGetSymbolAddress((void**)&WTl,  g_WTl);
    cudaGetSymbolAddress((void**)&VTh,  g_VTh);  cudaGetSymbolAddress((void**)&VTl,  g_VTl);

    const float scale = 0.03125f;   // 1/sqrt(1024)
    const long ND = (long)NROWS * DD;

    // Launch order matters for ncu (-s 5 -c 1 captures launch #6 = QKV gemm).
    // 1: embed
    {
        int total = NROWS * (DD / 4);
        embed_k<<<(total + 255) / 256, 256>>>(tokens, emb, pos, X);
    }
    // 2: ln1 (layer 0)
    ln_k<<<NROWS, 256>>>(X, Hf, Hh, Hl, g1, bln1, 0);
    // 3-5: weight prepass for Wq/Wk/Wv (z-batched over layers)
    tsplit(Wq, WTh,                     WTl,                     DD, DD, LL, (long)DD*DD, LYR_BLK);
    tsplit(Wk, WTh + (size_t)DD*DD,     WTl + (size_t)DD*DD,     DD, DD, LL, (long)DD*DD, LYR_BLK);
    tsplit(Wv, WTh + (size_t)2*DD*DD,   WTl + (size_t)2*DD*DD,   DD, DD, LL, (long)DD*DD, LYR_BLK);

    for (int l = 0; l < LL; l++) {
        size_t base = (size_t)l * LYR_BLK;
        const __nv_bfloat16* qkvTh = WTh + base;
        const __nv_bfloat16* qkvTl = WTl + base;
        const __nv_bfloat16* w1Th  = WTh + base + (size_t)3 * DD * DD;
        const __nv_bfloat16* w1Tl  = WTl + base + (size_t)3 * DD * DD;
        const __nv_bfloat16* w2Th  = WTh + base + (size_t)3 * DD * DD + (size_t)DD * FF;
        const __nv_bfloat16* w2Tl  = WTl + base + (size_t)3 * DD * DD + (size_t)DD * FF;
        const float* b1_l = b1 + (size_t)l * FF;
        const float* b2_l = b2 + (size_t)l * DD;

        // h = ln1(x)  (layer 0 hoisted above)
        if (l > 0)
            ln_k<<<NROWS, 256>>>(X, Hf, Hh, Hl, g1 + (size_t)l * DD, bln1 + (size_t)l * DD, 0);

        // q,k,v = h @ W  (launch #6 on l==0). fp32 only for V (z=2); split only q,k.
        gemm(Hh, Hl, qkvTh, qkvTl, QKVf, QKVh, QKVl, NROWS, DD, DD, 1.f,
             nullptr, nullptr, 0, 0, /*cf*/4, /*ch*/3, 3, NROWS/128,
             0, (long)DD * DD, ND, 0);

        if (l == 0) {
            // remaining weight prepass (after the capture-target launch)
            tsplit(w1, WTh + (size_t)3*DD*DD, WTl + (size_t)3*DD*DD, DD, FF, LL, (long)DD*FF, LYR_BLK);
            tsplit(w2, WTh + (size_t)3*DD*DD + (size_t)DD*FF, WTl + (size_t)3*DD*DD + (size_t)DD*FF,
                   FF, DD, LL, (long)FF*DD, LYR_BLK);
            tsplit(projw, WTh + PROJ_OFF, WTl + PROJ_OFF, DD, VV, 1, 0, 0);
        }

        // VT split (from V fp32, z=2 slice)
        tsplit(QKVf + 2 * ND, VTh, VTl, TT, DD, BB, (long)TT * DD, (long)DD * TT);

        // s = (q @ k^T) * scale   (causal tile-skip)
        gemm(QKVh, QKVl, QKVh + ND, QKVl + ND, S, nullptr, nullptr,
             TT, TT, DD, scale, nullptr, nullptr, 0, 1, 3, 0, BB, TT/128,
             (long)TT * DD, (long)TT * DD, (long)TT * TT, 0);

        // causal softmax -> split S
        {
            dim3 grid(TT, BB);
            softmax_k<<<grid, 256>>>(S, Sh, Sl);
        }

        // x = s @ v + x   (balanced causal fold: grid.y = 8, 2 row-tiles/CTA)
        gemm(Sh, Sl, VTh, VTl, X, nullptr, nullptr, TT, DD, TT, 1.f,
             nullptr, X, 0, 3, 3, 0, BB, TT/256,
             (long)TT * TT, (long)DD * TT, (long)TT * DD, (long)TT * DD);

        // y = ln2(x)  (fp32 needed as w2 addm)
        ln_k<<<NROWS, 256>>>(X, Hf, Hh, Hl, g2 + (size_t)l * DD, bln2 + (size_t)l * DD, 1);

        // ff = relu(y @ w1 + b1)  (split out only)
        gemm(Hh, Hl, w1Th, w1Tl, nullptr, Fh, Fl, NROWS, FF, DD, 1.f,
             b1_l, nullptr, 1, 0, 0, 1, 1, NROWS/128, 0, 0, 0, 0);

        // x = ff @ w2 + b2 + y  (fp32 + split out; split feeds final proj)
        gemm(Fh, Fl, w2Th, w2Tl, X, Xh, Xl, NROWS, DD, FF, 1.f,
             b2_l, Hf, 0, 0, 1, 1, 1, NROWS/128, 0, 0, 0, 0);
    }

    // logits = x @ proj_w + proj_b
    gemm(Xh, Xl, WTh + PROJ_OFF, WTl + PROJ_OFF, out, nullptr, nullptr,
         NROWS, VV, DD, 1.f, projb, nullptr, 0, 0, 1, 0, 1, NROWS/128,
         0, 0, 0, 0);
}

// round 13
// speedup vs baseline: 1.0327x; 1.0327x over previous
#include <cuda_runtime.h>
#include <cuda_bf16.h>
#include <math.h>
#include <stdint.h>

#define BB 2
#define TT 2048
#define DD 1024
#define LL 4
#define VV 32000
#define FF (4*DD)
#define NROWS (BB*TT)   // 4096

// WT scratch layout (elements): per layer: WqT,WkT,WvT (DD*DD each), w1T (DD*FF), w2T (FF*DD)
#define LYR_BLK (3*DD*DD + DD*FF + FF*DD)
#define PROJ_OFF ((size_t)LL*LYR_BLK)
#define WT_TOTAL (PROJ_OFF + (size_t)DD*VV)

// ---------------- scratch (device globals; no allocations allowed) ----------
__device__ float g_X[(size_t)NROWS*DD];
__device__ float g_Hf[(size_t)NROWS*DD];
__device__ float g_QKVf[(size_t)3*NROWS*DD];
__device__ float g_S[(size_t)BB*TT*TT];
__device__ __nv_bfloat16 g_Hh[(size_t)NROWS*DD],   g_Hl[(size_t)NROWS*DD];
__device__ __nv_bfloat16 g_Xh[(size_t)NROWS*DD],   g_Xl[(size_t)NROWS*DD];
__device__ __nv_bfloat16 g_QKVh[(size_t)3*NROWS*DD], g_QKVl[(size_t)3*NROWS*DD];
__device__ __nv_bfloat16 g_Sh[(size_t)BB*TT*TT],   g_Sl[(size_t)BB*TT*TT];
__device__ __nv_bfloat16 g_Fh[(size_t)NROWS*FF],   g_Fl[(size_t)NROWS*FF];
__device__ __nv_bfloat16 g_WTh[WT_TOTAL],          g_WTl[WT_TOTAL];
__device__ __nv_bfloat16 g_VTh[(size_t)BB*DD*TT],  g_VTl[(size_t)BB*DD*TT];

// ============================ helpers ========================================
__device__ __forceinline__ uint32_t smem_u32(const void* p) {
    uint32_t a;
    asm("{ .reg .u64 t; cvta.to.shared.u64 t, %1; cvt.u32.u64 %0, t; }" : "=r"(a) : "l"(p));
    return a;
}
// 64B-row swizzle: XOR byte bits [4:6) with bits [7:9)
#define SWZ64(o) ((o) ^ (((o) >> 3) & 0x30))

__device__ __forceinline__ void ldm_x4(uint32_t* r, uint32_t addr) {
    asm volatile("ldmatrix.sync.aligned.m8n8.x4.shared.b16 {%0,%1,%2,%3}, [%4];"
                 : "=r"(r[0]), "=r"(r[1]), "=r"(r[2]), "=r"(r[3]) : "r"(addr));
}
__device__ __forceinline__ void mma_bf16(float* d, const uint32_t* a, uint32_t b0, uint32_t b1) {
    asm volatile(
        "mma.sync.aligned.m16n8k16.row.col.f32.bf16.bf16.f32 "
        "{%0,%1,%2,%3}, {%4,%5,%6,%7}, {%8,%9}, {%0,%1,%2,%3};"
        : "+f"(d[0]), "+f"(d[1]), "+f"(d[2]), "+f"(d[3])
        : "r"(a[0]), "r"(a[1]), "r"(a[2]), "r"(a[3]), "r"(b0), "r"(b1));
}
__device__ __forceinline__ void cpa16(uint32_t dst, const void* src) {
    asm volatile("cp.async.cg.shared.global [%0], [%1], 16;" :: "r"(dst), "l"(src));
}
#define CP_COMMIT() asm volatile("cp.async.commit_group;" ::: "memory")
#define CP_WAIT2()  asm volatile("cp.async.wait_group 2;" ::: "memory")

__device__ __forceinline__ uint32_t pk2(__nv_bfloat16 a, __nv_bfloat16 b) {
    __nv_bfloat162 t = __halves2bfloat162(a, b);
    return *reinterpret_cast<uint32_t*>(&t);
}

// SMEM stage (32 KB): Ah @0, Al @8192, Bh @16384, Bl @24576. 128 rows x 32 bf16.
#define STG_SZ 32768
#define NSTG 4
#define SHM_TOTAL (NSTG*STG_SZ)
#define BK 32

// ---------------- all-bf16 split GEMM --------------------------------------
// C = alpha * (Ah+Al) @ (Bh+Bl)^T  (+bias)(+relu)(+addm), 3-term split MMA.
// A: [M][K] bf16 hi/lo. B: [N][K] bf16 hi/lo.
// Out: fp32 Cf if (cfMask>>z)&1; split Ch/Cl if (chMask>>z)&1.
// cmode: 0 none, 1 = causal tile-skip (QK^T), 2 = causal K-limit (A=S case).
__global__ __launch_bounds__(256) void gemm_k(
    const __nv_bfloat16* __restrict__ Ahp, const __nv_bfloat16* __restrict__ Alp,
    const __nv_bfloat16* __restrict__ Bhp, const __nv_bfloat16* __restrict__ Blp,
    float* __restrict__ Cf,
    __nv_bfloat16* __restrict__ Ch, __nv_bfloat16* __restrict__ Cl,
    int M, int N, int K, float alpha,
    const float* __restrict__ bias,
    const float* __restrict__ addm,
    int relu, int cmode, int cfMask, int chMask,
    long sA, long sB, long sC, long sAdd)
{
    extern __shared__ char smem[];
    const uint32_t smb = smem_u32(smem);
    const int tid = threadIdx.x;
    const long z = blockIdx.z;

    Ahp += z * sA; Alp += z * sA;
    Bhp += z * sB; Blp += z * sB;
    const bool wCf = Cf && ((cfMask >> z) & 1);
    const bool wCh = Ch && ((chMask >> z) & 1);
    if (Cf) Cf += z * sC;
    if (Ch) { Ch += z * sC; Cl += z * sC; }
    if (addm) addm += z * sAdd;

    const int rowBlk = blockIdx.y * 128;
    const int colBlk = blockIdx.x * 128;
    if (cmode == 1 && colBlk >= rowBlk + 128) return;   // fully-masked QK tile

    int kMax = K;
    if (cmode == 2) { kMax = rowBlk + 128; if (kMax > K) kMax = K; }
    const int nCh = kMax / BK;

    const int lr = tid >> 1, half = tid & 1;
    const __nv_bfloat16* pa_h = Ahp + (long)(rowBlk + lr) * K + half * 16;
    const __nv_bfloat16* pa_l = Alp + (long)(rowBlk + lr) * K + half * 16;
    const __nv_bfloat16* pb_h = Bhp + (long)(colBlk + lr) * K + half * 16;
    const __nv_bfloat16* pb_l = Blp + (long)(colBlk + lr) * K + half * 16;
    const uint32_t o0 = SWZ64((uint32_t)(lr * 64 + half * 32));
    const uint32_t o1 = SWZ64((uint32_t)(lr * 64 + half * 32 + 16));

    // prologue: issue first NSTG-1 = 3 chunks
#pragma unroll
    for (int s = 0; s < NSTG - 1; s++) {
        if (s < nCh) {
            uint32_t sb = smb + (uint32_t)s * STG_SZ;
            long k0 = (long)s * BK;
            cpa16(sb + o0,         pa_h + k0);  cpa16(sb + o1,         pa_h + k0 + 8);
            cpa16(sb + 8192  + o0, pa_l + k0);  cpa16(sb + 8192  + o1, pa_l + k0 + 8);
            cpa16(sb + 16384 + o0, pb_h + k0);  cpa16(sb + 16384 + o1, pb_h + k0 + 8);
            cpa16(sb + 24576 + o0, pb_l + k0);  cpa16(sb + 24576 + o1, pb_l + k0 + 8);
        }
        CP_COMMIT();
    }

    float acc[4][4][4];
#pragma unroll
    for (int i = 0; i < 4; i++)
#pragma unroll
        for (int j = 0; j < 4; j++)
#pragma unroll
            for (int k = 0; k < 4; k++) acc[i][j][k] = 0.f;

    const int w = tid >> 5, lane = tid & 31;
    const int wm = (w & 1) * 64;
    const int wn = (w >> 1) * 32;

    for (int c = 0; c < nCh; c++) {
        CP_WAIT2();
        __syncthreads();
        const uint32_t sb = smb + (uint32_t)(c & (NSTG - 1)) * STG_SZ;
#pragma unroll
        for (int ks = 0; ks < 2; ks++) {
            uint32_t ah[4][4], al[4][4];
#pragma unroll
            for (int mt = 0; mt < 4; mt++) {
                uint32_t off = SWZ64((uint32_t)((wm + mt * 16 + (lane & 15)) * 64
                                                + ks * 32 + (lane >> 4) * 16));
                ldm_x4(ah[mt], sb + off);
                ldm_x4(al[mt], sb + 8192 + off);
            }
            uint32_t bh[4][2], bl[4][2];
#pragma unroll
            for (int nt2 = 0; nt2 < 2; nt2++) {
                uint32_t off = SWZ64((uint32_t)((wn + nt2 * 16 + ((lane >> 4) & 1) * 8 + (lane & 7)) * 64
                                                + ks * 32 + ((lane >> 3) & 1) * 16));
                uint32_t r[4];
                ldm_x4(r, sb + 16384 + off);
                bh[nt2 * 2][0] = r[0]; bh[nt2 * 2][1] = r[1];
                bh[nt2 * 2 + 1][0] = r[2]; bh[nt2 * 2 + 1][1] = r[3];
                ldm_x4(r, sb + 24576 + off);
                bl[nt2 * 2][0] = r[0]; bl[nt2 * 2][1] = r[1];
                bl[nt2 * 2 + 1][0] = r[2]; bl[nt2 * 2 + 1][1] = r[3];
            }
#pragma unroll
            for (int mt = 0; mt < 4; mt++)
#pragma unroll
                for (int nt = 0; nt < 4; nt++) {
                    mma_bf16(acc[mt][nt], ah[mt], bh[nt][0], bh[nt][1]);
                    mma_bf16(acc[mt][nt], ah[mt], bl[nt][0], bl[nt][1]);
                    mma_bf16(acc[mt][nt], al[mt], bh[nt][0], bh[nt][1]);
                }
        }
        // issue chunk c+NSTG-1 into stage (c-1)&3 (safe: all passed this iter's barrier)
        if (c + NSTG - 1 < nCh) {
            uint32_t sbn = smb + (uint32_t)((c + NSTG - 1) & (NSTG - 1)) * STG_SZ;
            long k0 = (long)(c + NSTG - 1) * BK;
            cpa16(sbn + o0,         pa_h + k0);  cpa16(sbn + o1,         pa_h + k0 + 8);
            cpa16(sbn + 8192  + o0, pa_l + k0);  cpa16(sbn + 8192  + o1, pa_l + k0 + 8);
            cpa16(sbn + 16384 + o0, pb_h + k0);  cpa16(sbn + 16384 + o1, pb_h + k0 + 8);
            cpa16(sbn + 24576 + o0, pb_l + k0);  cpa16(sbn + 24576 + o1, pb_l + k0 + 8);
        }
        CP_COMMIT();
    }

    // ---- epilogue ----
#pragma unroll
    for (int mt = 0; mt < 4; mt++) {
        int r0 = rowBlk + wm + mt * 16 + (lane >> 2);
#pragma unroll
        for (int nt = 0; nt < 4; nt++) {
            int cc = colBlk + wn + nt * 8 + (lane & 3) * 2;
            float2 v0, v1;
            v0.x = acc[mt][nt][0] * alpha; v0.y = acc[mt][nt][1] * alpha;
            v1.x = acc[mt][nt][2] * alpha; v1.y = acc[mt][nt][3] * alpha;
            if (bias) {
                float2 bb = *reinterpret_cast<const float2*>(bias + cc);
                v0.x += bb.x; v0.y += bb.y; v1.x += bb.x; v1.y += bb.y;
            }
            if (relu) {
                v0.x = fmaxf(v0.x, 0.f); v0.y = fmaxf(v0.y, 0.f);
                v1.x = fmaxf(v1.x, 0.f); v1.y = fmaxf(v1.y, 0.f);
            }
            if (addm) {
                float2 a0 = *reinterpret_cast<const float2*>(addm + (long)r0 * N + cc);
                float2 a1 = *reinterpret_cast<const float2*>(addm + (long)(r0 + 8) * N + cc);
                v0.x += a0.x; v0.y += a0.y; v1.x += a1.x; v1.y += a1.y;
            }
            if (wCf) {
                *reinterpret_cast<float2*>(Cf + (long)r0 * N + cc) = v0;
                *reinterpret_cast<float2*>(Cf + (long)(r0 + 8) * N + cc) = v1;
            }
            if (wCh) {
                __nv_bfloat16 h0 = __float2bfloat16(v0.x), h1 = __float2bfloat16(v0.y);
                __nv_bfloat16 h2 = __float2bfloat16(v1.x), h3 = __float2bfloat16(v1.y);
                *reinterpret_cast<uint32_t*>(Ch + (long)r0 * N + cc)       = pk2(h0, h1);
                *reinterpret_cast<uint32_t*>(Ch + (long)(r0 + 8) * N + cc) = pk2(h2, h3);
                *reinterpret_cast<uint32_t*>(Cl + (long)r0 * N + cc) =
                    pk2(__float2bfloat16(v0.x - __bfloat162float(h0)),
                        __float2bfloat16(v0.y - __bfloat162float(h1)));
                *reinterpret_cast<uint32_t*>(Cl + (long)(r0 + 8) * N + cc) =
                    pk2(__float2bfloat16(v1.x - __bfloat162float(h2)),
                        __float2bfloat16(v1.y - __bfloat162float(h3)));
            }
        }
    }
}

// ---------------- transpose + bf16 split: W[R][C] -> T[C][R] hi/lo ----------
__global__ void tsplit_k(const float* __restrict__ W,
                         __nv_bfloat16* __restrict__ Th, __nv_bfloat16* __restrict__ Tl,
                         int R, int C, long sIn, long sOut)
{
    __shared__ float t[32][33];
    W  += (long)blockIdx.z * sIn;
    Th += (long)blockIdx.z * sOut;
    Tl += (long)blockIdx.z * sOut;
    int c0 = blockIdx.x * 32, r0 = blockIdx.y * 32;
    int tx = threadIdx.x, ty = threadIdx.y;
#pragma unroll
    for (int j = 0; j < 32; j += 8)
        t[ty + j][tx] = W[(long)(r0 + ty + j) * C + c0 + tx];
    __syncthreads();
#pragma unroll
    for (int j = 0; j < 32; j += 8) {
        int oc = c0 + ty + j;
        float v = t[tx][ty + j];
        __nv_bfloat16 h = __float2bfloat16(v);
        float lo = v - __bfloat162float(h);
        Th[(long)oc * R + r0 + tx] = h;
        Tl[(long)oc * R + r0 + tx] = __float2bfloat16(lo);
    }
}

// ---------------- embed: x = emb[tok] + pos ---------------------------------
__global__ void embed_k(const int* __restrict__ tok,
                        const float* __restrict__ emb,
                        const float* __restrict__ pos,
                        float* __restrict__ X)
{
    int idx = blockIdx.x * blockDim.x + threadIdx.x;
    int total = NROWS * (DD / 4);
    if (idx >= total) return;
    int d4 = idx % (DD / 4);
    int bt = idx / (DD / 4);
    int t = bt % TT;
    int token = tok[bt];
    float4 e = reinterpret_cast<const float4*>(emb + (size_t)token * DD)[d4];
    float4 p = reinterpret_cast<const float4*>(pos + (size_t)t * DD)[d4];
    float4 o; o.x = e.x + p.x; o.y = e.y + p.y; o.z = e.z + p.z; o.w = e.w + p.w;
    reinterpret_cast<float4*>(X + (size_t)bt * DD)[d4] = o;
}

// ---------------- layernorm: fp32 in -> (opt fp32) + bf16-split out ---------
__global__ void ln_k(const float* __restrict__ X,
                     float* __restrict__ Yf,
                     __nv_bfloat16* __restrict__ Yh, __nv_bfloat16* __restrict__ Yl,
                     const float* __restrict__ g, const float* __restrict__ b,
                     int writeF)
{
    int row = blockIdx.x;
    int tid = threadIdx.x;
    const float4* x4 = reinterpret_cast<const float4*>(X + (size_t)row * DD);
    float4 v = x4[tid];
    __shared__ float sh[256];

    float s = v.x + v.y + v.z + v.w;
    sh[tid] = s; __syncthreads();
    for (int o = 128; o > 0; o >>= 1) { if (tid < o) sh[tid] += sh[tid + o]; __syncthreads(); }
    float mu = sh[0] * (1.0f / DD);
    __syncthreads();

    float c0 = v.x - mu, c1 = v.y - mu, c2 = v.z - mu, c3 = v.w - mu;
    sh[tid] = c0 * c0 + c1 * c1 + c2 * c2 + c3 * c3; __syncthreads();
    for (int o = 128; o > 0; o >>= 1) { if (tid < o) sh[tid] += sh[tid + o]; __syncthreads(); }
    float inv = rsqrtf(sh[0] * (1.0f / DD) + 1e-5f);

    float4 gv = reinterpret_cast<const float4*>(g)[tid];
    float4 bv = reinterpret_cast<const float4*>(b)[tid];
    float4 o4;
    o4.x = c0 * inv * gv.x + bv.x;
    o4.y = c1 * inv * gv.y + bv.y;
    o4.z = c2 * inv * gv.z + bv.z;
    o4.w = c3 * inv * gv.w + bv.w;
    if (writeF)
        reinterpret_cast<float4*>(Yf + (size_t)row * DD)[tid] = o4;

    __nv_bfloat16 h0 = __float2bfloat16(o4.x), h1 = __float2bfloat16(o4.y);
    __nv_bfloat16 h2 = __float2bfloat16(o4.z), h3 = __float2bfloat16(o4.w);
    uint2 hv, lv;
    hv.x = pk2(h0, h1); hv.y = pk2(h2, h3);
    lv.x = pk2(__float2bfloat16(o4.x - __bfloat162float(h0)),
               __float2bfloat16(o4.y - __bfloat162float(h1)));
    lv.y = pk2(__float2bfloat16(o4.z - __bfloat162float(h2)),
               __float2bfloat16(o4.w - __bfloat162float(h3)));
    *reinterpret_cast<uint2*>(Yh + (size_t)row * DD + tid * 4) = hv;
    *reinterpret_cast<uint2*>(Yl + (size_t)row * DD + tid * 4) = lv;
}

// ---------------- causal softmax: fp32 S -> bf16-split out ------------------
// Row cached in smem; exp computed once per element; one global read.
__global__ void softmax_k(const float* __restrict__ S,
                          __nv_bfloat16* __restrict__ Sh, __nv_bfloat16* __restrict__ Sl)
{
    int t = blockIdx.x, b = blockIdx.y;
    int tid = threadIdx.x;
    const float* row = S + ((size_t)b * TT + t) * TT;
    __nv_bfloat16* rh = Sh + ((size_t)b * TT + t) * TT;
    __nv_bfloat16* rl = Sl + ((size_t)b * TT + t) * TT;
    __shared__ float ex[TT];
    __shared__ float sh[256];

    float mx = -1e30f;
    for (int c = tid; c <= t; c += 256) { float v = row[c]; ex[c] = v; mx = fmaxf(mx, v); }
    sh[tid] = mx; __syncthreads();
    for (int o = 128; o > 0; o >>= 1) { if (tid < o) sh[tid] = fmaxf(sh[tid], sh[tid + o]); __syncthreads(); }
    mx = sh[0]; __syncthreads();

    float sum = 0.f;
    for (int c = tid; c <= t; c += 256) { float e = __expf(ex[c] - mx); ex[c] = e; sum += e; }
    sh[tid] = sum; __syncthreads();
    for (int o = 128; o > 0; o >>= 1) { if (tid < o) sh[tid] += sh[tid + o]; __syncthreads(); }
    float inv = 1.0f / sh[0];

    for (int c = tid; c < TT; c += 256) {
        float p = (c <= t) ? ex[c] * inv : 0.0f;
        __nv_bfloat16 h = __float2bfloat16(p);
        rh[c] = h;
        rl[c] = __float2bfloat16(p - __bfloat162float(h));
    }
}

// ---------------- host-side dispatch -----------------------------------------
static void gemm(const __nv_bfloat16* Ah, const __nv_bfloat16* Al,
                 const __nv_bfloat16* Bh, const __nv_bfloat16* Bl,
                 float* Cf, __nv_bfloat16* Ch, __nv_bfloat16* Cl,
                 int M, int N, int K, float alpha,
                 const float* bias, const float* addm, int relu, int cmode,
                 int cfMask, int chMask, int batch,
                 long sA, long sB, long sC, long sAdd)
{
    dim3 grid(N / 128, M / 128, batch), blk(256);
    gemm_k<<<grid, blk, SHM_TOTAL>>>(Ah, Al, Bh, Bl, Cf, Ch, Cl,
                                     M, N, K, alpha, bias, addm, relu, cmode,
                                     cfMask, chMask, sA, sB, sC, sAdd);
}

static void tsplit(const float* W, __nv_bfloat16* Th, __nv_bfloat16* Tl,
                   int R, int C, int batch, long sIn, long sOut)
{
    dim3 g(C / 32, R / 32, batch), b(32, 8);
    tsplit_k<<<g, b>>>(W, Th, Tl, R, C, sIn, sOut);
}

extern "C" void kernel_launch(void* const* d_in, const int* in_sizes, int n_in,
                              void* d_out, int out_size)
{
    const int*   tokens = (const int*)  d_in[0];
    const float* emb    = (const float*)d_in[1];
    const float* pos    = (const float*)d_in[2];
    const float* Wq     = (const float*)d_in[3];
    const float* Wk     = (const float*)d_in[4];
    const float* Wv     = (const float*)d_in[5];
    const float* w1     = (const float*)d_in[6];
    const float* b1     = (const float*)d_in[7];
    const float* w2     = (const float*)d_in[8];
    const float* b2     = (const float*)d_in[9];
    const float* g1     = (const float*)d_in[10];
    const float* bln1   = (const float*)d_in[11];
    const float* g2     = (const float*)d_in[12];
    const float* bln2   = (const float*)d_in[13];
    const float* projw  = (const float*)d_in[14];
    const float* projb  = (const float*)d_in[15];
    float* out = (float*)d_out;

    cudaFuncSetAttribute(gemm_k, cudaFuncAttributeMaxDynamicSharedMemorySize, SHM_TOTAL);

    float *X, *Hf, *QKVf, *S;
    __nv_bfloat16 *Hh, *Hl, *Xh, *Xl, *QKVh, *QKVl, *Sh, *Sl, *Fh, *Fl, *WTh, *WTl, *VTh, *VTl;
    cudaGetSymbolAddress((void**)&X,    g_X);
    cudaGetSymbolAddress((void**)&Hf,   g_Hf);
    cudaGetSymbolAddress((void**)&QKVf, g_QKVf);
    cudaGetSymbolAddress((void**)&S,    g_S);
    cudaGetSymbolAddress((void**)&Hh,   g_Hh);   cudaGetSymbolAddress((void**)&Hl,   g_Hl);
    cudaGetSymbolAddress((void**)&Xh,   g_Xh);   cudaGetSymbolAddress((void**)&Xl,   g_Xl);
    cudaGetSymbolAddress((void**)&QKVh, g_QKVh); cudaGetSymbolAddress((void**)&QKVl, g_QKVl);
    cudaGetSymbolAddress((void**)&Sh,   g_Sh);   cudaGetSymbolAddress((void**)&Sl,   g_Sl);
    cudaGetSymbolAddress((void**)&Fh,   g_Fh);   cudaGetSymbolAddress((void**)&Fl,   g_Fl);
    cudaGetSymbolAddress((void**)&WTh,  g_WTh);  cudaGetSymbolAddress((void**)&WTl,  g_WTl);
    cudaGetSymbolAddress((void**)&VTh,  g_VTh);  cudaGetSymbolAddress((void**)&VTl,  g_VTl);

    const float scale = 0.03125f;   // 1/sqrt(1024)
    const long ND = (long)NROWS * DD;

    // ---- weight prepass: transpose + bf16 hi/lo split -----------------------
    for (int l = 0; l < LL; l++) {
        size_t base = (size_t)l * LYR_BLK;
        tsplit(Wq + (size_t)l * DD * DD, WTh + base,                   WTl + base,                   DD, DD, 1, 0, 0);
        tsplit(Wk + (size_t)l * DD * DD, WTh + base + (size_t)DD*DD,   WTl + base + (size_t)DD*DD,   DD, DD, 1, 0, 0);
        tsplit(Wv + (size_t)l * DD * DD, WTh + base + (size_t)2*DD*DD, WTl + base + (size_t)2*DD*DD, DD, DD, 1, 0, 0);
        tsplit(w1 + (size_t)l * DD * FF, WTh + base + (size_t)3*DD*DD, WTl + base + (size_t)3*DD*DD, DD, FF, 1, 0, 0);
        tsplit(w2 + (size_t)l * FF * DD, WTh + base + (size_t)3*DD*DD + (size_t)DD*FF,
                                         WTl + base + (size_t)3*DD*DD + (size_t)DD*FF, FF, DD, 1, 0, 0);
    }
    tsplit(projw, WTh + PROJ_OFF, WTl + PROJ_OFF, DD, VV, 1, 0, 0);

    // ---- embed --------------------------------------------------------------
    {
        int total = NROWS * (DD / 4);
        embed_k<<<(total + 255) / 256, 256>>>(tokens, emb, pos, X);
    }

    for (int l = 0; l < LL; l++) {
        size_t base = (size_t)l * LYR_BLK;
        const __nv_bfloat16* qkvTh = WTh + base;
        const __nv_bfloat16* qkvTl = WTl + base;
        const __nv_bfloat16* w1Th  = WTh + base + (size_t)3 * DD * DD;
        const __nv_bfloat16* w1Tl  = WTl + base + (size_t)3 * DD * DD;
        const __nv_bfloat16* w2Th  = WTh + base + (size_t)3 * DD * DD + (size_t)DD * FF;
        const __nv_bfloat16* w2Tl  = WTl + base + (size_t)3 * DD * DD + (size_t)DD * FF;
        const float* b1_l = b1 + (size_t)l * FF;
        const float* b2_l = b2 + (size_t)l * DD;

        // h = ln1(x)  (split only; fp32 copy is dead)
        ln_k<<<NROWS, 256>>>(X, Hf, Hh, Hl, g1 + (size_t)l * DD, bln1 + (size_t)l * DD, 0);

        // q,k,v = h @ W  (fp32 only for V slice z=2; split only for q,k)
        gemm(Hh, Hl, qkvTh, qkvTl, QKVf, QKVh, QKVl, NROWS, DD, DD, 1.f,
             nullptr, nullptr, 0, 0, /*cf*/4, /*ch*/3, 3,
             0, (long)DD * DD, ND, 0);

        // VT split (from V fp32, z=2 slice)
        tsplit(QKVf + 2 * ND, VTh, VTl, TT, DD, BB, (long)TT * DD, (long)DD * TT);

        // s = (q @ k^T) * scale   (causal tile-skip; out fp32)
        gemm(QKVh, QKVl, QKVh + ND, QKVl + ND, S, nullptr, nullptr,
             TT, TT, DD, scale, nullptr, nullptr, 0, 1, 3, 0, BB,
             (long)TT * DD, (long)TT * DD, (long)TT * TT, 0);

        // causal softmax -> split S
        {
            dim3 grid(TT, BB);
            softmax_k<<<grid, 256>>>(S, Sh, Sl);
        }

        // x = s @ v + x   (K-limit via causal zeros; out fp32)
        gemm(Sh, Sl, VTh, VTl, X, nullptr, nullptr, TT, DD, TT, 1.f,
             nullptr, X, 0, 2, 3, 0, BB,
             (long)TT * TT, (long)DD * TT, (long)TT * DD, (long)TT * DD);

        // y = ln2(x)  (fp32 needed as w2 addm)
        ln_k<<<NROWS, 256>>>(X, Hf, Hh, Hl, g2 + (size_t)l * DD, bln2 + (size_t)l * DD, 1);

        // ff = relu(y @ w1 + b1)  (split out only)
        gemm(Hh, Hl, w1Th, w1Tl, nullptr, Fh, Fl, NROWS, FF, DD, 1.f,
             b1_l, nullptr, 1, 0, 0, 1, 1, 0, 0, 0, 0);

        // x = ff @ w2 + b2 + y  (fp32 always; split only on last layer for proj)
        gemm(Fh, Fl, w2Th, w2Tl, X, Xh, Xl, NROWS, DD, FF, 1.f,
             b2_l, Hf, 0, 0, 1, (l == LL - 1) ? 1 : 0, 1, 0, 0, 0, 0);
    }

    // logits = x @ proj_w + proj_b
    gemm(Xh, Xl, WTh + PROJ_OFF, WTl + PROJ_OFF, out, nullptr, nullptr,
         NROWS, VV, DD, 1.f, projb, nullptr, 0, 0, 1, 0, 1,
         0, 0, 0, 0);
}

// round 14
// speedup vs baseline: 1.3154x; 1.2738x over previous
#include <cuda_runtime.h>
#include <cuda_fp16.h>
#include <math.h>
#include <stdint.h>

#define BB 2
#define TT 2048
#define DD 1024
#define LL 4
#define VV 32000
#define FF (4*DD)
#define NROWS (BB*TT)   // 4096

// WT scratch layout (elements): per layer: WqT,WkT,WvT (DD*DD each), w1T (DD*FF), w2T (FF*DD)
#define LYR_BLK (3*DD*DD + DD*FF + FF*DD)
#define PROJ_OFF ((size_t)LL*LYR_BLK)
#define WT_TOTAL (PROJ_OFF + (size_t)DD*VV)

// ---------------- scratch (device globals; no allocations allowed) ----------
__device__ float g_X[(size_t)NROWS*DD];
__device__ float g_Hf[(size_t)NROWS*DD];
__device__ float g_QKVf[(size_t)3*NROWS*DD];
__device__ float g_S[(size_t)BB*TT*TT];
__device__ __half g_Hh[(size_t)NROWS*DD],   g_Hl[(size_t)NROWS*DD];
__device__ __half g_Xh[(size_t)NROWS*DD],   g_Xl[(size_t)NROWS*DD];
__device__ __half g_QKVh[(size_t)3*NROWS*DD], g_QKVl[(size_t)3*NROWS*DD];
__device__ __half g_Sh[(size_t)BB*TT*TT],   g_Sl[(size_t)BB*TT*TT];
__device__ __half g_Fh[(size_t)NROWS*FF],   g_Fl[(size_t)NROWS*FF];
__device__ __half g_WTh[WT_TOTAL],          g_WTl[WT_TOTAL];
__device__ __half g_VTh[(size_t)BB*DD*TT],  g_VTl[(size_t)BB*DD*TT];

// ============================ helpers ========================================
__device__ __forceinline__ uint32_t smem_u32(const void* p) {
    uint32_t a;
    asm("{ .reg .u64 t; cvta.to.shared.u64 t, %1; cvt.u32.u64 %0, t; }" : "=r"(a) : "l"(p));
    return a;
}
// 64B-row swizzle: XOR byte bits [4:6) with bits [7:9)
#define SWZ64(o) ((o) ^ (((o) >> 3) & 0x30))

__device__ __forceinline__ void ldm_x4(uint32_t* r, uint32_t addr) {
    asm volatile("ldmatrix.sync.aligned.m8n8.x4.shared.b16 {%0,%1,%2,%3}, [%4];"
                 : "=r"(r[0]), "=r"(r[1]), "=r"(r[2]), "=r"(r[3]) : "r"(addr));
}
__device__ __forceinline__ void mma_f16(float* d, const uint32_t* a, uint32_t b0, uint32_t b1) {
    asm volatile(
        "mma.sync.aligned.m16n8k16.row.col.f32.f16.f16.f32 "
        "{%0,%1,%2,%3}, {%4,%5,%6,%7}, {%8,%9}, {%0,%1,%2,%3};"
        : "+f"(d[0]), "+f"(d[1]), "+f"(d[2]), "+f"(d[3])
        : "r"(a[0]), "r"(a[1]), "r"(a[2]), "r"(a[3]), "r"(b0), "r"(b1));
}
__device__ __forceinline__ void cpa16(uint32_t dst, const void* src) {
    asm volatile("cp.async.cg.shared.global [%0], [%1], 16;" :: "r"(dst), "l"(src));
}
#define CP_COMMIT() asm volatile("cp.async.commit_group;" ::: "memory")
#define CP_WAIT2()  asm volatile("cp.async.wait_group 2;" ::: "memory")

__device__ __forceinline__ uint32_t pk2(__half a, __half b) {
    __half2 t = __halves2half2(a, b);
    return *reinterpret_cast<uint32_t*>(&t);
}

// SMEM stage (32 KB): Ah @0, Al @8192, Bh @16384, Bl @24576. 128 rows x 32 f16.
#define STG_SZ 32768
#define NSTG 4
#define SHM_TOTAL (NSTG*STG_SZ)
#define BK 32

// ---------------- split-fp16 GEMM -------------------------------------------
// TERMS=2: C = alpha*(Ah+Al)@Bh^T      (A exact, B 11-bit)
// TERMS=3: C = alpha*(Ah+Al)@(Bh+Bl)^T (both ~exact)
// A: [M][K] f16 hi/lo. B: [N][K] f16 hi(/lo).
// Out: fp32 Cf if (cfMask>>z)&1; f16 Ch if (chMask>>z)&1; f16 Cl if (clMask>>z)&1.
// cmode: 0 none, 1 = causal tile-skip (QK^T), 2 = causal K-limit (A=S case).
template<int TERMS>
__global__ __launch_bounds__(256) void gemm_k(
    const __half* __restrict__ Ahp, const __half* __restrict__ Alp,
    const __half* __restrict__ Bhp, const __half* __restrict__ Blp,
    float* __restrict__ Cf,
    __half* __restrict__ Ch, __half* __restrict__ Cl,
    int M, int N, int K, float alpha,
    const float* __restrict__ bias,
    const float* __restrict__ addm,
    int relu, int cmode, int cfMask, int chMask, int clMask,
    long sA, long sB, long sC, long sAdd)
{
    extern __shared__ char smem[];
    const uint32_t smb = smem_u32(smem);
    const int tid = threadIdx.x;
    const long z = blockIdx.z;

    Ahp += z * sA; Alp += z * sA;
    Bhp += z * sB; if (TERMS == 3) Blp += z * sB;
    const bool wCf = Cf && ((cfMask >> z) & 1);
    const bool wCh = Ch && ((chMask >> z) & 1);
    const bool wCl = Cl && ((clMask >> z) & 1);
    if (Cf) Cf += z * sC;
    if (Ch) Ch += z * sC;
    if (Cl) Cl += z * sC;
    if (addm) addm += z * sAdd;

    const int rowBlk = blockIdx.y * 128;
    const int colBlk = blockIdx.x * 128;
    if (cmode == 1 && colBlk >= rowBlk + 128) return;   // fully-masked QK tile

    int kMax = K;
    if (cmode == 2) { kMax = rowBlk + 128; if (kMax > K) kMax = K; }
    const int nCh = kMax / BK;

    const int lr = tid >> 1, half = tid & 1;
    const __half* pa_h = Ahp + (long)(rowBlk + lr) * K + half * 16;
    const __half* pa_l = Alp + (long)(rowBlk + lr) * K + half * 16;
    const __half* pb_h = Bhp + (long)(colBlk + lr) * K + half * 16;
    const __half* pb_l = (TERMS == 3) ? (Blp + (long)(colBlk + lr) * K + half * 16) : nullptr;
    const uint32_t o0 = SWZ64((uint32_t)(lr * 64 + half * 32));
    const uint32_t o1 = SWZ64((uint32_t)(lr * 64 + half * 32 + 16));

    // prologue: issue first NSTG-1 = 3 chunks
#pragma unroll
    for (int s = 0; s < NSTG - 1; s++) {
        if (s < nCh) {
            uint32_t sb = smb + (uint32_t)s * STG_SZ;
            long k0 = (long)s * BK;
            cpa16(sb + o0,         pa_h + k0);  cpa16(sb + o1,         pa_h + k0 + 8);
            cpa16(sb + 8192  + o0, pa_l + k0);  cpa16(sb + 8192  + o1, pa_l + k0 + 8);
            cpa16(sb + 16384 + o0, pb_h + k0);  cpa16(sb + 16384 + o1, pb_h + k0 + 8);
            if (TERMS == 3) {
                cpa16(sb + 24576 + o0, pb_l + k0);  cpa16(sb + 24576 + o1, pb_l + k0 + 8);
            }
        }
        CP_COMMIT();
    }

    float acc[4][4][4];
#pragma unroll
    for (int i = 0; i < 4; i++)
#pragma unroll
        for (int j = 0; j < 4; j++)
#pragma unroll
            for (int k = 0; k < 4; k++) acc[i][j][k] = 0.f;

    const int w = tid >> 5, lane = tid & 31;
    const int wm = (w & 1) * 64;
    const int wn = (w >> 1) * 32;

    for (int c = 0; c < nCh; c++) {
        CP_WAIT2();
        __syncthreads();
        const uint32_t sb = smb + (uint32_t)(c & (NSTG - 1)) * STG_SZ;
#pragma unroll
        for (int ks = 0; ks < 2; ks++) {
            uint32_t ah[4][4], al[4][4];
#pragma unroll
            for (int mt = 0; mt < 4; mt++) {
                uint32_t off = SWZ64((uint32_t)((wm + mt * 16 + (lane & 15)) * 64
                                                + ks * 32 + (lane >> 4) * 16));
                ldm_x4(ah[mt], sb + off);
                ldm_x4(al[mt], sb + 8192 + off);
            }
            uint32_t bh[4][2], bl[4][2];
#pragma unroll
            for (int nt2 = 0; nt2 < 2; nt2++) {
                uint32_t off = SWZ64((uint32_t)((wn + nt2 * 16 + ((lane >> 4) & 1) * 8 + (lane & 7)) * 64
                                                + ks * 32 + ((lane >> 3) & 1) * 16));
                uint32_t r[4];
                ldm_x4(r, sb + 16384 + off);
                bh[nt2 * 2][0] = r[0]; bh[nt2 * 2][1] = r[1];
                bh[nt2 * 2 + 1][0] = r[2]; bh[nt2 * 2 + 1][1] = r[3];
                if (TERMS == 3) {
                    ldm_x4(r, sb + 24576 + off);
                    bl[nt2 * 2][0] = r[0]; bl[nt2 * 2][1] = r[1];
                    bl[nt2 * 2 + 1][0] = r[2]; bl[nt2 * 2 + 1][1] = r[3];
                }
            }
#pragma unroll
            for (int mt = 0; mt < 4; mt++)
#pragma unroll
                for (int nt = 0; nt < 4; nt++) {
                    mma_f16(acc[mt][nt], ah[mt], bh[nt][0], bh[nt][1]);
                    if (TERMS == 3)
                        mma_f16(acc[mt][nt], ah[mt], bl[nt][0], bl[nt][1]);
                    mma_f16(acc[mt][nt], al[mt], bh[nt][0], bh[nt][1]);
                }
        }
        // issue chunk c+NSTG-1 into stage (c-1)&3 (safe: all passed this iter's barrier)
        if (c + NSTG - 1 < nCh) {
            uint32_t sbn = smb + (uint32_t)((c + NSTG - 1) & (NSTG - 1)) * STG_SZ;
            long k0 = (long)(c + NSTG - 1) * BK;
            cpa16(sbn + o0,         pa_h + k0);  cpa16(sbn + o1,         pa_h + k0 + 8);
            cpa16(sbn + 8192  + o0, pa_l + k0);  cpa16(sbn + 8192  + o1, pa_l + k0 + 8);
            cpa16(sbn + 16384 + o0, pb_h + k0);  cpa16(sbn + 16384 + o1, pb_h + k0 + 8);
            if (TERMS == 3) {
                cpa16(sbn + 24576 + o0, pb_l + k0);  cpa16(sbn + 24576 + o1, pb_l + k0 + 8);
            }
        }
        CP_COMMIT();
    }

    // ---- epilogue ----
#pragma unroll
    for (int mt = 0; mt < 4; mt++) {
        int r0 = rowBlk + wm + mt * 16 + (lane >> 2);
#pragma unroll
        for (int nt = 0; nt < 4; nt++) {
            int cc = colBlk + wn + nt * 8 + (lane & 3) * 2;
            float2 v0, v1;
            v0.x = acc[mt][nt][0] * alpha; v0.y = acc[mt][nt][1] * alpha;
            v1.x = acc[mt][nt][2] * alpha; v1.y = acc[mt][nt][3] * alpha;
            if (bias) {
                float2 bb = *reinterpret_cast<const float2*>(bias + cc);
                v0.x += bb.x; v0.y += bb.y; v1.x += bb.x; v1.y += bb.y;
            }
            if (relu) {
                v0.x = fmaxf(v0.x, 0.f); v0.y = fmaxf(v0.y, 0.f);
                v1.x = fmaxf(v1.x, 0.f); v1.y = fmaxf(v1.y, 0.f);
            }
            if (addm) {
                float2 a0 = *reinterpret_cast<const float2*>(addm + (long)r0 * N + cc);
                float2 a1 = *reinterpret_cast<const float2*>(addm + (long)(r0 + 8) * N + cc);
                v0.x += a0.x; v0.y += a0.y; v1.x += a1.x; v1.y += a1.y;
            }
            if (wCf) {
                *reinterpret_cast<float2*>(Cf + (long)r0 * N + cc) = v0;
                *reinterpret_cast<float2*>(Cf + (long)(r0 + 8) * N + cc) = v1;
            }
            if (wCh || wCl) {
                __half h0 = __float2half_rn(v0.x), h1 = __float2half_rn(v0.y);
                __half h2 = __float2half_rn(v1.x), h3 = __float2half_rn(v1.y);
                if (wCh) {
                    *reinterpret_cast<uint32_t*>(Ch + (long)r0 * N + cc)       = pk2(h0, h1);
                    *reinterpret_cast<uint32_t*>(Ch + (long)(r0 + 8) * N + cc) = pk2(h2, h3);
                }
                if (wCl) {
                    *reinterpret_cast<uint32_t*>(Cl + (long)r0 * N + cc) =
                        pk2(__float2half_rn(v0.x - __half2float(h0)),
                            __float2half_rn(v0.y - __half2float(h1)));
                    *reinterpret_cast<uint32_t*>(Cl + (long)(r0 + 8) * N + cc) =
                        pk2(__float2half_rn(v1.x - __half2float(h2)),
                            __float2half_rn(v1.y - __half2float(h3)));
                }
            }
        }
    }
}

// ---------------- transpose + f16 split: W[R][C] -> T[C][R] hi(/lo) ---------
__global__ void tsplit_k(const float* __restrict__ W,
                         __half* __restrict__ Th, __half* __restrict__ Tl,
                         int R, int C, long sIn, long sOut, int writeL)
{
    __shared__ float t[32][33];
    W  += (long)blockIdx.z * sIn;
    Th += (long)blockIdx.z * sOut;
    Tl += (long)blockIdx.z * sOut;
    int c0 = blockIdx.x * 32, r0 = blockIdx.y * 32;
    int tx = threadIdx.x, ty = threadIdx.y;
#pragma unroll
    for (int j = 0; j < 32; j += 8)
        t[ty + j][tx] = W[(long)(r0 + ty + j) * C + c0 + tx];
    __syncthreads();
#pragma unroll
    for (int j = 0; j < 32; j += 8) {
        int oc = c0 + ty + j;
        float v = t[tx][ty + j];
        __half h = __float2half_rn(v);
        Th[(long)oc * R + r0 + tx] = h;
        if (writeL)
            Tl[(long)oc * R + r0 + tx] = __float2half_rn(v - __half2float(h));
    }
}

// ---------------- embed: x = emb[tok] + pos ---------------------------------
__global__ void embed_k(const int* __restrict__ tok,
                        const float* __restrict__ emb,
                        const float* __restrict__ pos,
                        float* __restrict__ X)
{
    int idx = blockIdx.x * blockDim.x + threadIdx.x;
    int total = NROWS * (DD / 4);
    if (idx >= total) return;
    int d4 = idx % (DD / 4);
    int bt = idx / (DD / 4);
    int t = bt % TT;
    int token = tok[bt];
    float4 e = reinterpret_cast<const float4*>(emb + (size_t)token * DD)[d4];
    float4 p = reinterpret_cast<const float4*>(pos + (size_t)t * DD)[d4];
    float4 o; o.x = e.x + p.x; o.y = e.y + p.y; o.z = e.z + p.z; o.w = e.w + p.w;
    reinterpret_cast<float4*>(X + (size_t)bt * DD)[d4] = o;
}

// ---------------- layernorm: fp32 in -> (opt fp32) + f16-split out ----------
__global__ void ln_k(const float* __restrict__ X,
                     float* __restrict__ Yf,
                     __half* __restrict__ Yh, __half* __restrict__ Yl,
                     const float* __restrict__ g, const float* __restrict__ b,
                     int writeF)
{
    int row = blockIdx.x;
    int tid = threadIdx.x;
    const float4* x4 = reinterpret_cast<const float4*>(X + (size_t)row * DD);
    float4 v = x4[tid];
    __shared__ float sh[256];

    float s = v.x + v.y + v.z + v.w;
    sh[tid] = s; __syncthreads();
    for (int o = 128; o > 0; o >>= 1) { if (tid < o) sh[tid] += sh[tid + o]; __syncthreads(); }
    float mu = sh[0] * (1.0f / DD);
    __syncthreads();

    float c0 = v.x - mu, c1 = v.y - mu, c2 = v.z - mu, c3 = v.w - mu;
    sh[tid] = c0 * c0 + c1 * c1 + c2 * c2 + c3 * c3; __syncthreads();
    for (int o = 128; o > 0; o >>= 1) { if (tid < o) sh[tid] += sh[tid + o]; __syncthreads(); }
    float inv = rsqrtf(sh[0] * (1.0f / DD) + 1e-5f);

    float4 gv = reinterpret_cast<const float4*>(g)[tid];
    float4 bv = reinterpret_cast<const float4*>(b)[tid];
    float4 o4;
    o4.x = c0 * inv * gv.x + bv.x;
    o4.y = c1 * inv * gv.y + bv.y;
    o4.z = c2 * inv * gv.z + bv.z;
    o4.w = c3 * inv * gv.w + bv.w;
    if (writeF)
        reinterpret_cast<float4*>(Yf + (size_t)row * DD)[tid] = o4;

    __half h0 = __float2half_rn(o4.x), h1 = __float2half_rn(o4.y);
    __half h2 = __float2half_rn(o4.z), h3 = __float2half_rn(o4.w);
    uint2 hv, lv;
    hv.x = pk2(h0, h1); hv.y = pk2(h2, h3);
    lv.x = pk2(__float2half_rn(o4.x - __half2float(h0)),
               __float2half_rn(o4.y - __half2float(h1)));
    lv.y = pk2(__float2half_rn(o4.z - __half2float(h2)),
               __float2half_rn(o4.w - __half2float(h3)));
    *reinterpret_cast<uint2*>(Yh + (size_t)row * DD + tid * 4) = hv;
    *reinterpret_cast<uint2*>(Yl + (size_t)row * DD + tid * 4) = lv;
}

// ---------------- causal softmax: fp32 S -> f16-split out -------------------
__global__ void softmax_k(const float* __restrict__ S,
                          __half* __restrict__ Sh, __half* __restrict__ Sl)
{
    int t = blockIdx.x, b = blockIdx.y;
    int tid = threadIdx.x;
    const float* row = S + ((size_t)b * TT + t) * TT;
    __half* rh = Sh + ((size_t)b * TT + t) * TT;
    __half* rl = Sl + ((size_t)b * TT + t) * TT;
    __shared__ float ex[TT];
    __shared__ float sh[256];

    float mx = -1e30f;
    for (int c = tid; c <= t; c += 256) { float v = row[c]; ex[c] = v; mx = fmaxf(mx, v); }
    sh[tid] = mx; __syncthreads();
    for (int o = 128; o > 0; o >>= 1) { if (tid < o) sh[tid] = fmaxf(sh[tid], sh[tid + o]); __syncthreads(); }
    mx = sh[0]; __syncthreads();

    float sum = 0.f;
    for (int c = tid; c <= t; c += 256) { float e = __expf(ex[c] - mx); ex[c] = e; sum += e; }
    sh[tid] = sum; __syncthreads();
    for (int o = 128; o > 0; o >>= 1) { if (tid < o) sh[tid] += sh[tid + o]; __syncthreads(); }
    float inv = 1.0f / sh[0];

    for (int c = tid; c < TT; c += 256) {
        float p = (c <= t) ? ex[c] * inv : 0.0f;
        __half h = __float2half_rn(p);
        rh[c] = h;
        rl[c] = __float2half_rn(p - __half2float(h));
    }
}

// ---------------- host-side dispatch -----------------------------------------
static void gemm(int terms,
                 const __half* Ah, const __half* Al,
                 const __half* Bh, const __half* Bl,
                 float* Cf, __half* Ch, __half* Cl,
                 int M, int N, int K, float alpha,
                 const float* bias, const float* addm, int relu, int cmode,
                 int cfMask, int chMask, int clMask, int batch,
                 long sA, long sB, long sC, long sAdd)
{
    dim3 grid(N / 128, M / 128, batch), blk(256);
    if (terms == 3)
        gemm_k<3><<<grid, blk, SHM_TOTAL>>>(Ah, Al, Bh, Bl, Cf, Ch, Cl,
                                            M, N, K, alpha, bias, addm, relu, cmode,
                                            cfMask, chMask, clMask, sA, sB, sC, sAdd);
    else
        gemm_k<2><<<grid, blk, SHM_TOTAL>>>(Ah, Al, Bh, Bl, Cf, Ch, Cl,
                                            M, N, K, alpha, bias, addm, relu, cmode,
                                            cfMask, chMask, clMask, sA, sB, sC, sAdd);
}

static void tsplit(const float* W, __half* Th, __half* Tl,
                   int R, int C, int batch, long sIn, long sOut, int writeL)
{
    dim3 g(C / 32, R / 32, batch), b(32, 8);
    tsplit_k<<<g, b>>>(W, Th, Tl, R, C, sIn, sOut, writeL);
}

extern "C" void kernel_launch(void* const* d_in, const int* in_sizes, int n_in,
                              void* d_out, int out_size)
{
    const int*   tokens = (const int*)  d_in[0];
    const float* emb    = (const float*)d_in[1];
    const float* pos    = (const float*)d_in[2];
    const float* Wq     = (const float*)d_in[3];
    const float* Wk     = (const float*)d_in[4];
    const float* Wv     = (const float*)d_in[5];
    const float* w1     = (const float*)d_in[6];
    const float* b1     = (const float*)d_in[7];
    const float* w2     = (const float*)d_in[8];
    const float* b2     = (const float*)d_in[9];
    const float* g1     = (const float*)d_in[10];
    const float* bln1   = (const float*)d_in[11];
    const float* g2     = (const float*)d_in[12];
    const float* bln2   = (const float*)d_in[13];
    const float* projw  = (const float*)d_in[14];
    const float* projb  = (const float*)d_in[15];
    float* out = (float*)d_out;

    cudaFuncSetAttribute(gemm_k<2>, cudaFuncAttributeMaxDynamicSharedMemorySize, SHM_TOTAL);
    cudaFuncSetAttribute(gemm_k<3>, cudaFuncAttributeMaxDynamicSharedMemorySize, SHM_TOTAL);

    float *X, *Hf, *QKVf, *S;
    __half *Hh, *Hl, *Xh, *Xl, *QKVh, *QKVl, *Sh, *Sl, *Fh, *Fl, *WTh, *WTl, *VTh, *VTl;
    cudaGetSymbolAddress((void**)&X,    g_X);
    cudaGetSymbolAddress((void**)&Hf,   g_Hf);
    cudaGetSymbolAddress((void**)&QKVf, g_QKVf);
    cudaGetSymbolAddress((void**)&S,    g_S);
    cudaGetSymbolAddress((void**)&Hh,   g_Hh);   cudaGetSymbolAddress((void**)&Hl,   g_Hl);
    cudaGetSymbolAddress((void**)&Xh,   g_Xh);   cudaGetSymbolAddress((void**)&Xl,   g_Xl);
    cudaGetSymbolAddress((void**)&QKVh, g_QKVh); cudaGetSymbolAddress((void**)&QKVl, g_QKVl);
    cudaGetSymbolAddress((void**)&Sh,   g_Sh);   cudaGetSymbolAddress((void**)&Sl,   g_Sl);
    cudaGetSymbolAddress((void**)&Fh,   g_Fh);   cudaGetSymbolAddress((void**)&Fl,   g_Fl);
    cudaGetSymbolAddress((void**)&WTh,  g_WTh);  cudaGetSymbolAddress((void**)&WTl,  g_WTl);
    cudaGetSymbolAddress((void**)&VTh,  g_VTh);  cudaGetSymbolAddress((void**)&VTl,  g_VTl);

    const float scale = 0.03125f;   // 1/sqrt(1024)
    const long ND = (long)NROWS * DD;

    // ---- weight prepass: transpose + f16 split (hi only; weights are B-role) -
    for (int l = 0; l < LL; l++) {
        size_t base = (size_t)l * LYR_BLK;
        tsplit(Wq + (size_t)l * DD * DD, WTh + base,                   WTl + base,                   DD, DD, 1, 0, 0, 0);
        tsplit(Wk + (size_t)l * DD * DD, WTh + base + (size_t)DD*DD,   WTl + base + (size_t)DD*DD,   DD, DD, 1, 0, 0, 0);
        tsplit(Wv + (size_t)l * DD * DD, WTh + base + (size_t)2*DD*DD, WTl + base + (size_t)2*DD*DD, DD, DD, 1, 0, 0, 0);
        tsplit(w1 + (size_t)l * DD * FF, WTh + base + (size_t)3*DD*DD, WTl + base + (size_t)3*DD*DD, DD, FF, 1, 0, 0, 0);
        tsplit(w2 + (size_t)l * FF * DD, WTh + base + (size_t)3*DD*DD + (size_t)DD*FF,
                                         WTl + base + (size_t)3*DD*DD + (size_t)DD*FF, FF, DD, 1, 0, 0, 0);
    }
    tsplit(projw, WTh + PROJ_OFF, WTl + PROJ_OFF, DD, VV, 1, 0, 0, 0);

    // ---- embed --------------------------------------------------------------
    {
        int total = NROWS * (DD / 4);
        embed_k<<<(total + 255) / 256, 256>>>(tokens, emb, pos, X);
    }

    for (int l = 0; l < LL; l++) {
        size_t base = (size_t)l * LYR_BLK;
        const __half* qkvTh = WTh + base;
        const __half* w1Th  = WTh + base + (size_t)3 * DD * DD;
        const __half* w2Th  = WTh + base + (size_t)3 * DD * DD + (size_t)DD * FF;
        const float* b1_l = b1 + (size_t)l * FF;
        const float* b2_l = b2 + (size_t)l * DD;

        // h = ln1(x)  (split only)
        ln_k<<<NROWS, 256>>>(X, Hf, Hh, Hl, g1 + (size_t)l * DD, bln1 + (size_t)l * DD, 0);

        // q,k,v = h @ W   [2-term: A=H exact, B=W 11-bit]
        // outs: V fp32 (z=2); Q,K h+l (needed exact for 3-term QK)
        gemm(2, Hh, Hl, qkvTh, nullptr, QKVf, QKVh, QKVl, NROWS, DD, DD, 1.f,
             nullptr, nullptr, 0, 0, /*cf*/4, /*ch*/3, /*cl*/3, 3,
             0, (long)DD * DD, ND, 0);

        // VT split (h+l; V is B-role in 3-term AV)
        tsplit(QKVf + 2 * ND, VTh, VTl, TT, DD, BB, (long)TT * DD, (long)DD * TT, 1);

        // s = (q @ k^T) * scale   [3-term; causal tile-skip]
        gemm(3, QKVh, QKVl, QKVh + ND, QKVl + ND, S, nullptr, nullptr,
             TT, TT, DD, scale, nullptr, nullptr, 0, 1, 3, 0, 0, BB,
             (long)TT * DD, (long)TT * DD, (long)TT * TT, 0);

        // causal softmax -> split S
        {
            dim3 grid(TT, BB);
            softmax_k<<<grid, 256>>>(S, Sh, Sl);
        }

        // x = s @ v + x   [3-term; causal K-limit]
        gemm(3, Sh, Sl, VTh, VTl, X, nullptr, nullptr, TT, DD, TT, 1.f,
             nullptr, X, 0, 2, 3, 0, 0, BB,
             (long)TT * TT, (long)DD * TT, (long)TT * DD, (long)TT * DD);

        // y = ln2(x)  (fp32 needed as w2 addm)
        ln_k<<<NROWS, 256>>>(X, Hf, Hh, Hl, g2 + (size_t)l * DD, bln2 + (size_t)l * DD, 1);

        // ff = relu(y @ w1 + b1)  [2-term; split out (A-role in w2)]
        gemm(2, Hh, Hl, w1Th, nullptr, nullptr, Fh, Fl, NROWS, FF, DD, 1.f,
             b1_l, nullptr, 1, 0, 0, 1, 1, 1, 0, 0, 0, 0);

        // x = ff @ w2 + b2 + y  [2-term; fp32 + (last layer) split for proj]
        int lm = (l == LL - 1) ? 1 : 0;
        gemm(2, Fh, Fl, w2Th, nullptr, X, Xh, Xl, NROWS, DD, FF, 1.f,
             b2_l, Hf, 0, 0, 1, lm, lm, 1, 0, 0, 0, 0);
    }

    // logits = x @ proj_w + proj_b  [2-term]
    gemm(2, Xh, Xl, WTh + PROJ_OFF, nullptr, out, nullptr, nullptr,
         NROWS, VV, DD, 1.f, projb, nullptr, 0, 0, 1, 0, 0, 1,
         0, 0, 0, 0);
}

// round 15
// speedup vs baseline: 1.3956x; 1.0609x over previous
#include <cuda_runtime.h>
#include <cuda_fp16.h>
#include <math.h>
#include <stdint.h>

#define BB 2
#define TT 2048
#define DD 1024
#define LL 4
#define VV 32000
#define FF (4*DD)
#define NROWS (BB*TT)   // 4096

// WT scratch layout (elements): per layer: WqT,WkT,WvT (DD*DD each), w1T (DD*FF), w2T (FF*DD)
#define LYR_BLK (3*DD*DD + DD*FF + FF*DD)
#define PROJ_OFF ((size_t)LL*LYR_BLK)
#define WT_TOTAL (PROJ_OFF + (size_t)DD*VV)

// ---------------- scratch (device globals; no allocations allowed) ----------
__device__ float g_X[(size_t)NROWS*DD];
__device__ float g_Hf[(size_t)NROWS*DD];
__device__ float g_QKVf[(size_t)3*NROWS*DD];
__device__ float g_S[(size_t)BB*TT*TT];
__device__ __half g_Hh[(size_t)NROWS*DD],   g_Hl[(size_t)NROWS*DD];
__device__ __half g_Xh[(size_t)NROWS*DD],   g_Xl[(size_t)NROWS*DD];
__device__ __half g_QKVh[(size_t)3*NROWS*DD], g_QKVl[(size_t)3*NROWS*DD];
__device__ __half g_Sh[(size_t)BB*TT*TT],   g_Sl[(size_t)BB*TT*TT];
__device__ __half g_Fh[(size_t)NROWS*FF],   g_Fl[(size_t)NROWS*FF];
__device__ __half g_WTh[WT_TOTAL],          g_WTl[WT_TOTAL];
__device__ __half g_VTh[(size_t)BB*DD*TT],  g_VTl[(size_t)BB*DD*TT];

// ============================ helpers ========================================
__device__ __forceinline__ uint32_t smem_u32(const void* p) {
    uint32_t a;
    asm("{ .reg .u64 t; cvta.to.shared.u64 t, %1; cvt.u32.u64 %0, t; }" : "=r"(a) : "l"(p));
    return a;
}
// 64B-row swizzle: XOR byte bits [4:6) with bits [7:9)
#define SWZ64(o) ((o) ^ (((o) >> 3) & 0x30))

__device__ __forceinline__ void ldm_x4(uint32_t* r, uint32_t addr) {
    asm volatile("ldmatrix.sync.aligned.m8n8.x4.shared.b16 {%0,%1,%2,%3}, [%4];"
                 : "=r"(r[0]), "=r"(r[1]), "=r"(r[2]), "=r"(r[3]) : "r"(addr));
}
__device__ __forceinline__ void mma_f16(float* d, const uint32_t* a, uint32_t b0, uint32_t b1) {
    asm volatile(
        "mma.sync.aligned.m16n8k16.row.col.f32.f16.f16.f32 "
        "{%0,%1,%2,%3}, {%4,%5,%6,%7}, {%8,%9}, {%0,%1,%2,%3};"
        : "+f"(d[0]), "+f"(d[1]), "+f"(d[2]), "+f"(d[3])
        : "r"(a[0]), "r"(a[1]), "r"(a[2]), "r"(a[3]), "r"(b0), "r"(b1));
}
__device__ __forceinline__ void cpa16(uint32_t dst, const void* src) {
    asm volatile("cp.async.cg.shared.global [%0], [%1], 16;" :: "r"(dst), "l"(src));
}
#define CP_COMMIT() asm volatile("cp.async.commit_group;" ::: "memory")
#define CP_WAIT2()  asm volatile("cp.async.wait_group 2;" ::: "memory")

__device__ __forceinline__ uint32_t pk2(__half a, __half b) {
    __half2 t = __halves2half2(a, b);
    return *reinterpret_cast<uint32_t*>(&t);
}

#define STG_SZ 32768
#define NSTG 4
#define SHM_TOTAL (NSTG*STG_SZ)
#define BK 32

// =============== 2-term wide GEMM: tile 128(M) x 256(N) =====================
// C = alpha*(Ah+Al)@Bh^T (+bias)(+relu)(+addm).  A:[M][K] f16 hi/lo, B:[N][K] f16.
// Stage (32KB): Ah @0 (8K), Al @8192, Bh @16384 (16K, 256 rows x 32 f16).
// Warps 2(m)x4(n), warp tile 64x64. Outs per z-masks as before.
__global__ __launch_bounds__(256) void gemm2w_k(
    const __half* __restrict__ Ahp, const __half* __restrict__ Alp,
    const __half* __restrict__ Bhp,
    float* __restrict__ Cf,
    __half* __restrict__ Ch, __half* __restrict__ Cl,
    int M, int N, int K, float alpha,
    const float* __restrict__ bias,
    const float* __restrict__ addm,
    int relu, int cfMask, int chMask, int clMask,
    long sA, long sB, long sC, long sAdd)
{
    extern __shared__ char smem[];
    const uint32_t smb = smem_u32(smem);
    const int tid = threadIdx.x;
    const long z = blockIdx.z;

    Ahp += z * sA; Alp += z * sA;
    Bhp += z * sB;
    const bool wCf = Cf && ((cfMask >> z) & 1);
    const bool wCh = Ch && ((chMask >> z) & 1);
    const bool wCl = Cl && ((clMask >> z) & 1);
    if (Cf) Cf += z * sC;
    if (Ch) Ch += z * sC;
    if (Cl) Cl += z * sC;
    if (addm) addm += z * sAdd;

    const int rowBlk = blockIdx.y * 128;
    const int colBlk = blockIdx.x * 256;
    const int nCh = K / BK;

    const int lr = tid >> 1, half = tid & 1;
    const __half* pa_h = Ahp + (long)(rowBlk + lr) * K + half * 16;
    const __half* pa_l = Alp + (long)(rowBlk + lr) * K + half * 16;
    const __half* pb   = Bhp + (long)(colBlk + tid) * K;
    const uint32_t oA0 = SWZ64((uint32_t)(lr * 64 + half * 32));
    const uint32_t oA1 = SWZ64((uint32_t)(lr * 64 + half * 32 + 16));
    const uint32_t oB0 = SWZ64((uint32_t)(tid * 64));
    const uint32_t oB1 = SWZ64((uint32_t)(tid * 64 + 16));
    const uint32_t oB2 = SWZ64((uint32_t)(tid * 64 + 32));
    const uint32_t oB3 = SWZ64((uint32_t)(tid * 64 + 48));

    // prologue: issue first NSTG-1 = 3 chunks
#pragma unroll
    for (int s = 0; s < NSTG - 1; s++) {
        if (s < nCh) {
            uint32_t sb = smb + (uint32_t)s * STG_SZ;
            long k0 = (long)s * BK;
            cpa16(sb + oA0,         pa_h + k0);  cpa16(sb + oA1,         pa_h + k0 + 8);
            cpa16(sb + 8192 + oA0,  pa_l + k0);  cpa16(sb + 8192 + oA1,  pa_l + k0 + 8);
            cpa16(sb + 16384 + oB0, pb + k0);      cpa16(sb + 16384 + oB1, pb + k0 + 8);
            cpa16(sb + 16384 + oB2, pb + k0 + 16); cpa16(sb + 16384 + oB3, pb + k0 + 24);
        }
        CP_COMMIT();
    }

    float acc[4][8][4];
#pragma unroll
    for (int i = 0; i < 4; i++)
#pragma unroll
        for (int j = 0; j < 8; j++)
#pragma unroll
            for (int k = 0; k < 4; k++) acc[i][j][k] = 0.f;

    const int w = tid >> 5, lane = tid & 31;
    const int wm = (w & 1) * 64;
    const int wn = (w >> 1) * 64;

    for (int c = 0; c < nCh; c++) {
        CP_WAIT2();
        __syncthreads();
        const uint32_t sb = smb + (uint32_t)(c & (NSTG - 1)) * STG_SZ;
#pragma unroll
        for (int ks = 0; ks < 2; ks++) {
            uint32_t bh[8][2];
#pragma unroll
            for (int nt2 = 0; nt2 < 4; nt2++) {
                uint32_t off = SWZ64((uint32_t)((wn + nt2 * 16 + ((lane >> 4) & 1) * 8 + (lane & 7)) * 64
                                                + ks * 32 + ((lane >> 3) & 1) * 16));
                uint32_t r[4];
                ldm_x4(r, sb + 16384 + off);
                bh[nt2 * 2][0] = r[0]; bh[nt2 * 2][1] = r[1];
                bh[nt2 * 2 + 1][0] = r[2]; bh[nt2 * 2 + 1][1] = r[3];
            }
#pragma unroll
            for (int mt = 0; mt < 4; mt++) {
                uint32_t off = SWZ64((uint32_t)((wm + mt * 16 + (lane & 15)) * 64
                                                + ks * 32 + (lane >> 4) * 16));
                uint32_t ah4[4], al4[4];
                ldm_x4(ah4, sb + off);
                ldm_x4(al4, sb + 8192 + off);
#pragma unroll
                for (int nt = 0; nt < 8; nt++) mma_f16(acc[mt][nt], ah4, bh[nt][0], bh[nt][1]);
#pragma unroll
                for (int nt = 0; nt < 8; nt++) mma_f16(acc[mt][nt], al4, bh[nt][0], bh[nt][1]);
            }
        }
        if (c + NSTG - 1 < nCh) {
            uint32_t sbn = smb + (uint32_t)((c + NSTG - 1) & (NSTG - 1)) * STG_SZ;
            long k0 = (long)(c + NSTG - 1) * BK;
            cpa16(sbn + oA0,         pa_h + k0);  cpa16(sbn + oA1,         pa_h + k0 + 8);
            cpa16(sbn + 8192 + oA0,  pa_l + k0);  cpa16(sbn + 8192 + oA1,  pa_l + k0 + 8);
            cpa16(sbn + 16384 + oB0, pb + k0);      cpa16(sbn + 16384 + oB1, pb + k0 + 8);
            cpa16(sbn + 16384 + oB2, pb + k0 + 16); cpa16(sbn + 16384 + oB3, pb + k0 + 24);
        }
        CP_COMMIT();
    }

    // ---- epilogue ----
#pragma unroll
    for (int mt = 0; mt < 4; mt++) {
        int r0 = rowBlk + wm + mt * 16 + (lane >> 2);
#pragma unroll
        for (int nt = 0; nt < 8; nt++) {
            int cc = colBlk + wn + nt * 8 + (lane & 3) * 2;
            float2 v0, v1;
            v0.x = acc[mt][nt][0] * alpha; v0.y = acc[mt][nt][1] * alpha;
            v1.x = acc[mt][nt][2] * alpha; v1.y = acc[mt][nt][3] * alpha;
            if (bias) {
                float2 bb = *reinterpret_cast<const float2*>(bias + cc);
                v0.x += bb.x; v0.y += bb.y; v1.x += bb.x; v1.y += bb.y;
            }
            if (relu) {
                v0.x = fmaxf(v0.x, 0.f); v0.y = fmaxf(v0.y, 0.f);
                v1.x = fmaxf(v1.x, 0.f); v1.y = fmaxf(v1.y, 0.f);
            }
            if (addm) {
                float2 a0 = *reinterpret_cast<const float2*>(addm + (long)r0 * N + cc);
                float2 a1 = *reinterpret_cast<const float2*>(addm + (long)(r0 + 8) * N + cc);
                v0.x += a0.x; v0.y += a0.y; v1.x += a1.x; v1.y += a1.y;
            }
            if (wCf) {
                *reinterpret_cast<float2*>(Cf + (long)r0 * N + cc) = v0;
                *reinterpret_cast<float2*>(Cf + (long)(r0 + 8) * N + cc) = v1;
            }
            if (wCh || wCl) {
                __half h0 = __float2half_rn(v0.x), h1 = __float2half_rn(v0.y);
                __half h2 = __float2half_rn(v1.x), h3 = __float2half_rn(v1.y);
                if (wCh) {
                    *reinterpret_cast<uint32_t*>(Ch + (long)r0 * N + cc)       = pk2(h0, h1);
                    *reinterpret_cast<uint32_t*>(Ch + (long)(r0 + 8) * N + cc) = pk2(h2, h3);
                }
                if (wCl) {
                    *reinterpret_cast<uint32_t*>(Cl + (long)r0 * N + cc) =
                        pk2(__float2half_rn(v0.x - __half2float(h0)),
                            __float2half_rn(v0.y - __half2float(h1)));
                    *reinterpret_cast<uint32_t*>(Cl + (long)(r0 + 8) * N + cc) =
                        pk2(__float2half_rn(v1.x - __half2float(h2)),
                            __float2half_rn(v1.y - __half2float(h3)));
                }
            }
        }
    }
}

// =============== 3-term GEMM: tile 128x128 (QK^T and A·V) ====================
// C = alpha*(Ah+Al)@(Bh+Bl)^T. cmode: 1 = causal tile-skip, 2 = causal K-limit.
__global__ __launch_bounds__(256) void gemm3_k(
    const __half* __restrict__ Ahp, const __half* __restrict__ Alp,
    const __half* __restrict__ Bhp, const __half* __restrict__ Blp,
    float* __restrict__ Cf,
    int M, int N, int K, float alpha,
    const float* __restrict__ addm,
    int cmode,
    long sA, long sB, long sC, long sAdd)
{
    extern __shared__ char smem[];
    const uint32_t smb = smem_u32(smem);
    const int tid = threadIdx.x;
    const long z = blockIdx.z;

    Ahp += z * sA; Alp += z * sA;
    Bhp += z * sB; Blp += z * sB;
    Cf += z * sC;
    if (addm) addm += z * sAdd;

    const int rowBlk = blockIdx.y * 128;
    const int colBlk = blockIdx.x * 128;
    if (cmode == 1 && colBlk >= rowBlk + 128) return;

    int kMax = K;
    if (cmode == 2) { kMax = rowBlk + 128; if (kMax > K) kMax = K; }
    const int nCh = kMax / BK;

    const int lr = tid >> 1, half = tid & 1;
    const __half* pa_h = Ahp + (long)(rowBlk + lr) * K + half * 16;
    const __half* pa_l = Alp + (long)(rowBlk + lr) * K + half * 16;
    const __half* pb_h = Bhp + (long)(colBlk + lr) * K + half * 16;
    const __half* pb_l = Blp + (long)(colBlk + lr) * K + half * 16;
    const uint32_t o0 = SWZ64((uint32_t)(lr * 64 + half * 32));
    const uint32_t o1 = SWZ64((uint32_t)(lr * 64 + half * 32 + 16));

#pragma unroll
    for (int s = 0; s < NSTG - 1; s++) {
        if (s < nCh) {
            uint32_t sb = smb + (uint32_t)s * STG_SZ;
            long k0 = (long)s * BK;
            cpa16(sb + o0,         pa_h + k0);  cpa16(sb + o1,         pa_h + k0 + 8);
            cpa16(sb + 8192  + o0, pa_l + k0);  cpa16(sb + 8192  + o1, pa_l + k0 + 8);
            cpa16(sb + 16384 + o0, pb_h + k0);  cpa16(sb + 16384 + o1, pb_h + k0 + 8);
            cpa16(sb + 24576 + o0, pb_l + k0);  cpa16(sb + 24576 + o1, pb_l + k0 + 8);
        }
        CP_COMMIT();
    }

    float acc[4][4][4];
#pragma unroll
    for (int i = 0; i < 4; i++)
#pragma unroll
        for (int j = 0; j < 4; j++)
#pragma unroll
            for (int k = 0; k < 4; k++) acc[i][j][k] = 0.f;

    const int w = tid >> 5, lane = tid & 31;
    const int wm = (w & 1) * 64;
    const int wn = (w >> 1) * 32;

    for (int c = 0; c < nCh; c++) {
        CP_WAIT2();
        __syncthreads();
        const uint32_t sb = smb + (uint32_t)(c & (NSTG - 1)) * STG_SZ;
#pragma unroll
        for (int ks = 0; ks < 2; ks++) {
            uint32_t ah[4][4], al[4][4];
#pragma unroll
            for (int mt = 0; mt < 4; mt++) {
                uint32_t off = SWZ64((uint32_t)((wm + mt * 16 + (lane & 15)) * 64
                                                + ks * 32 + (lane >> 4) * 16));
                ldm_x4(ah[mt], sb + off);
                ldm_x4(al[mt], sb + 8192 + off);
            }
            uint32_t bh[4][2], bl[4][2];
#pragma unroll
            for (int nt2 = 0; nt2 < 2; nt2++) {
                uint32_t off = SWZ64((uint32_t)((wn + nt2 * 16 + ((lane >> 4) & 1) * 8 + (lane & 7)) * 64
                                                + ks * 32 + ((lane >> 3) & 1) * 16));
                uint32_t r[4];
                ldm_x4(r, sb + 16384 + off);
                bh[nt2 * 2][0] = r[0]; bh[nt2 * 2][1] = r[1];
                bh[nt2 * 2 + 1][0] = r[2]; bh[nt2 * 2 + 1][1] = r[3];
                ldm_x4(r, sb + 24576 + off);
                bl[nt2 * 2][0] = r[0]; bl[nt2 * 2][1] = r[1];
                bl[nt2 * 2 + 1][0] = r[2]; bl[nt2 * 2 + 1][1] = r[3];
            }
#pragma unroll
            for (int mt = 0; mt < 4; mt++)
#pragma unroll
                for (int nt = 0; nt < 4; nt++) {
                    mma_f16(acc[mt][nt], ah[mt], bh[nt][0], bh[nt][1]);
                    mma_f16(acc[mt][nt], ah[mt], bl[nt][0], bl[nt][1]);
                    mma_f16(acc[mt][nt], al[mt], bh[nt][0], bh[nt][1]);
                }
        }
        if (c + NSTG - 1 < nCh) {
            uint32_t sbn = smb + (uint32_t)((c + NSTG - 1) & (NSTG - 1)) * STG_SZ;
            long k0 = (long)(c + NSTG - 1) * BK;
            cpa16(sbn + o0,         pa_h + k0);  cpa16(sbn + o1,         pa_h + k0 + 8);
            cpa16(sbn + 8192  + o0, pa_l + k0);  cpa16(sbn + 8192  + o1, pa_l + k0 + 8);
            cpa16(sbn + 16384 + o0, pb_h + k0);  cpa16(sbn + 16384 + o1, pb_h + k0 + 8);
            cpa16(sbn + 24576 + o0, pb_l + k0);  cpa16(sbn + 24576 + o1, pb_l + k0 + 8);
        }
        CP_COMMIT();
    }

#pragma unroll
    for (int mt = 0; mt < 4; mt++) {
        int r0 = rowBlk + wm + mt * 16 + (lane >> 2);
#pragma unroll
        for (int nt = 0; nt < 4; nt++) {
            int cc = colBlk + wn + nt * 8 + (lane & 3) * 2;
            float2 v0, v1;
            v0.x = acc[mt][nt][0] * alpha; v0.y = acc[mt][nt][1] * alpha;
            v1.x = acc[mt][nt][2] * alpha; v1.y = acc[mt][nt][3] * alpha;
            if (addm) {
                float2 a0 = *reinterpret_cast<const float2*>(addm + (long)r0 * N + cc);
                float2 a1 = *reinterpret_cast<const float2*>(addm + (long)(r0 + 8) * N + cc);
                v0.x += a0.x; v0.y += a0.y; v1.x += a1.x; v1.y += a1.y;
            }
            *reinterpret_cast<float2*>(Cf + (long)r0 * N + cc) = v0;
            *reinterpret_cast<float2*>(Cf + (long)(r0 + 8) * N + cc) = v1;
        }
    }
}

// ---------------- transpose + f16 split: W[R][C] -> T[C][R] hi(/lo) ---------
__global__ void tsplit_k(const float* __restrict__ W,
                         __half* __restrict__ Th, __half* __restrict__ Tl,
                         int R, int C, long sIn, long sOut, int writeL)
{
    __shared__ float t[32][33];
    W  += (long)blockIdx.z * sIn;
    Th += (long)blockIdx.z * sOut;
    Tl += (long)blockIdx.z * sOut;
    int c0 = blockIdx.x * 32, r0 = blockIdx.y * 32;
    int tx = threadIdx.x, ty = threadIdx.y;
#pragma unroll
    for (int j = 0; j < 32; j += 8)
        t[ty + j][tx] = W[(long)(r0 + ty + j) * C + c0 + tx];
    __syncthreads();
#pragma unroll
    for (int j = 0; j < 32; j += 8) {
        int oc = c0 + ty + j;
        float v = t[tx][ty + j];
        __half h = __float2half_rn(v);
        Th[(long)oc * R + r0 + tx] = h;
        if (writeL)
            Tl[(long)oc * R + r0 + tx] = __float2half_rn(v - __half2float(h));
    }
}

// ---------------- embed: x = emb[tok] + pos ---------------------------------
__global__ void embed_k(const int* __restrict__ tok,
                        const float* __restrict__ emb,
                        const float* __restrict__ pos,
                        float* __restrict__ X)
{
    int idx = blockIdx.x * blockDim.x + threadIdx.x;
    int total = NROWS * (DD / 4);
    if (idx >= total) return;
    int d4 = idx % (DD / 4);
    int bt = idx / (DD / 4);
    int t = bt % TT;
    int token = tok[bt];
    float4 e = reinterpret_cast<const float4*>(emb + (size_t)token * DD)[d4];
    float4 p = reinterpret_cast<const float4*>(pos + (size_t)t * DD)[d4];
    float4 o; o.x = e.x + p.x; o.y = e.y + p.y; o.z = e.z + p.z; o.w = e.w + p.w;
    reinterpret_cast<float4*>(X + (size_t)bt * DD)[d4] = o;
}

// ---------------- layernorm: fp32 in -> (opt fp32) + f16-split out ----------
__global__ void ln_k(const float* __restrict__ X,
                     float* __restrict__ Yf,
                     __half* __restrict__ Yh, __half* __restrict__ Yl,
                     const float* __restrict__ g, const float* __restrict__ b,
                     int writeF)
{
    int row = blockIdx.x;
    int tid = threadIdx.x;
    const float4* x4 = reinterpret_cast<const float4*>(X + (size_t)row * DD);
    float4 v = x4[tid];
    __shared__ float sh[256];

    float s = v.x + v.y + v.z + v.w;
    sh[tid] = s; __syncthreads();
    for (int o = 128; o > 0; o >>= 1) { if (tid < o) sh[tid] += sh[tid + o]; __syncthreads(); }
    float mu = sh[0] * (1.0f / DD);
    __syncthreads();

    float c0 = v.x - mu, c1 = v.y - mu, c2 = v.z - mu, c3 = v.w - mu;
    sh[tid] = c0 * c0 + c1 * c1 + c2 * c2 + c3 * c3; __syncthreads();
    for (int o = 128; o > 0; o >>= 1) { if (tid < o) sh[tid] += sh[tid + o]; __syncthreads(); }
    float inv = rsqrtf(sh[0] * (1.0f / DD) + 1e-5f);

    float4 gv = reinterpret_cast<const float4*>(g)[tid];
    float4 bv = reinterpret_cast<const float4*>(b)[tid];
    float4 o4;
    o4.x = c0 * inv * gv.x + bv.x;
    o4.y = c1 * inv * gv.y + bv.y;
    o4.z = c2 * inv * gv.z + bv.z;
    o4.w = c3 * inv * gv.w + bv.w;
    if (writeF)
        reinterpret_cast<float4*>(Yf + (size_t)row * DD)[tid] = o4;

    __half h0 = __float2half_rn(o4.x), h1 = __float2half_rn(o4.y);
    __half h2 = __float2half_rn(o4.z), h3 = __float2half_rn(o4.w);
    uint2 hv, lv;
    hv.x = pk2(h0, h1); hv.y = pk2(h2, h3);
    lv.x = pk2(__float2half_rn(o4.x - __half2float(h0)),
               __float2half_rn(o4.y - __half2float(h1)));
    lv.y = pk2(__float2half_rn(o4.z - __half2float(h2)),
               __float2half_rn(o4.w - __half2float(h3)));
    *reinterpret_cast<uint2*>(Yh + (size_t)row * DD + tid * 4) = hv;
    *reinterpret_cast<uint2*>(Yl + (size_t)row * DD + tid * 4) = lv;
}

// ---------------- causal softmax: fp32 S -> f16-split out -------------------
__global__ void softmax_k(const float* __restrict__ S,
                          __half* __restrict__ Sh, __half* __restrict__ Sl)
{
    int t = blockIdx.x, b = blockIdx.y;
    int tid = threadIdx.x;
    const float* row = S + ((size_t)b * TT + t) * TT;
    __half* rh = Sh + ((size_t)b * TT + t) * TT;
    __half* rl = Sl + ((size_t)b * TT + t) * TT;
    __shared__ float ex[TT];
    __shared__ float sh[256];

    float mx = -1e30f;
    for (int c = tid; c <= t; c += 256) { float v = row[c]; ex[c] = v; mx = fmaxf(mx, v); }
    sh[tid] = mx; __syncthreads();
    for (int o = 128; o > 0; o >>= 1) { if (tid < o) sh[tid] = fmaxf(sh[tid], sh[tid + o]); __syncthreads(); }
    mx = sh[0]; __syncthreads();

    float sum = 0.f;
    for (int c = tid; c <= t; c += 256) { float e = __expf(ex[c] - mx); ex[c] = e; sum += e; }
    sh[tid] = sum; __syncthreads();
    for (int o = 128; o > 0; o >>= 1) { if (tid < o) sh[tid] += sh[tid + o]; __syncthreads(); }
    float inv = 1.0f / sh[0];

    for (int c = tid; c < TT; c += 256) {
        float p = (c <= t) ? ex[c] * inv : 0.0f;
        __half h = __float2half_rn(p);
        rh[c] = h;
        rl[c] = __float2half_rn(p - __half2float(h));
    }
}

// ---------------- host-side dispatch -----------------------------------------
static void gemm2(const __half* Ah, const __half* Al, const __half* Bh,
                  float* Cf, __half* Ch, __half* Cl,
                  int M, int N, int K, float alpha,
                  const float* bias, const float* addm, int relu,
                  int cfMask, int chMask, int clMask, int batch,
                  long sA, long sB, long sC, long sAdd)
{
    dim3 grid(N / 256, M / 128, batch), blk(256);
    gemm2w_k<<<grid, blk, SHM_TOTAL>>>(Ah, Al, Bh, Cf, Ch, Cl,
                                       M, N, K, alpha, bias, addm, relu,
                                       cfMask, chMask, clMask, sA, sB, sC, sAdd);
}

static void gemm3(const __half* Ah, const __half* Al,
                  const __half* Bh, const __half* Bl,
                  float* Cf, int M, int N, int K, float alpha,
                  const float* addm, int cmode, int batch,
                  long sA, long sB, long sC, long sAdd)
{
    dim3 grid(N / 128, M / 128, batch), blk(256);
    gemm3_k<<<grid, blk, SHM_TOTAL>>>(Ah, Al, Bh, Bl, Cf,
                                      M, N, K, alpha, addm, cmode,
                                      sA, sB, sC, sAdd);
}

static void tsplit(const float* W, __half* Th, __half* Tl,
                   int R, int C, int batch, long sIn, long sOut, int writeL)
{
    dim3 g(C / 32, R / 32, batch), b(32, 8);
    tsplit_k<<<g, b>>>(W, Th, Tl, R, C, sIn, sOut, writeL);
}

extern "C" void kernel_launch(void* const* d_in, const int* in_sizes, int n_in,
                              void* d_out, int out_size)
{
    const int*   tokens = (const int*)  d_in[0];
    const float* emb    = (const float*)d_in[1];
    const float* pos    = (const float*)d_in[2];
    const float* Wq     = (const float*)d_in[3];
    const float* Wk     = (const float*)d_in[4];
    const float* Wv     = (const float*)d_in[5];
    const float* w1     = (const float*)d_in[6];
    const float* b1     = (const float*)d_in[7];
    const float* w2     = (const float*)d_in[8];
    const float* b2     = (const float*)d_in[9];
    const float* g1     = (const float*)d_in[10];
    const float* bln1   = (const float*)d_in[11];
    const float* g2     = (const float*)d_in[12];
    const float* bln2   = (const float*)d_in[13];
    const float* projw  = (const float*)d_in[14];
    const float* projb  = (const float*)d_in[15];
    float* out = (float*)d_out;

    cudaFuncSetAttribute(gemm2w_k, cudaFuncAttributeMaxDynamicSharedMemorySize, SHM_TOTAL);
    cudaFuncSetAttribute(gemm3_k,  cudaFuncAttributeMaxDynamicSharedMemorySize, SHM_TOTAL);

    float *X, *Hf, *QKVf, *S;
    __half *Hh, *Hl, *Xh, *Xl, *QKVh, *QKVl, *Sh, *Sl, *Fh, *Fl, *WTh, *WTl, *VTh, *VTl;
    cudaGetSymbolAddress((void**)&X,    g_X);
    cudaGetSymbolAddress((void**)&Hf,   g_Hf);
    cudaGetSymbolAddress((void**)&QKVf, g_QKVf);
    cudaGetSymbolAddress((void**)&S,    g_S);
    cudaGetSymbolAddress((void**)&Hh,   g_Hh);   cudaGetSymbolAddress((void**)&Hl,   g_Hl);
    cudaGetSymbolAddress((void**)&Xh,   g_Xh);   cudaGetSymbolAddress((void**)&Xl,   g_Xl);
    cudaGetSymbolAddress((void**)&QKVh, g_QKVh); cudaGetSymbolAddress((void**)&QKVl, g_QKVl);
    cudaGetSymbolAddress((void**)&Sh,   g_Sh);   cudaGetSymbolAddress((void**)&Sl,   g_Sl);
    cudaGetSymbolAddress((void**)&Fh,   g_Fh);   cudaGetSymbolAddress((void**)&Fl,   g_Fl);
    cudaGetSymbolAddress((void**)&WTh,  g_WTh);  cudaGetSymbolAddress((void**)&WTl,  g_WTl);
    cudaGetSymbolAddress((void**)&VTh,  g_VTh);  cudaGetSymbolAddress((void**)&VTl,  g_VTl);

    const float scale = 0.03125f;   // 1/sqrt(1024)
    const long ND = (long)NROWS * DD;

    // ---- weight prepass: transpose + f16 (hi only; weights are B-role) ------
    for (int l = 0; l < LL; l++) {
        size_t base = (size_t)l * LYR_BLK;
        tsplit(Wq + (size_t)l * DD * DD, WTh + base,                   WTl + base,                   DD, DD, 1, 0, 0, 0);
        tsplit(Wk + (size_t)l * DD * DD, WTh + base + (size_t)DD*DD,   WTl + base + (size_t)DD*DD,   DD, DD, 1, 0, 0, 0);
        tsplit(Wv + (size_t)l * DD * DD, WTh + base + (size_t)2*DD*DD, WTl + base + (size_t)2*DD*DD, DD, DD, 1, 0, 0, 0);
        tsplit(w1 + (size_t)l * DD * FF, WTh + base + (size_t)3*DD*DD, WTl + base + (size_t)3*DD*DD, DD, FF, 1, 0, 0, 0);
        tsplit(w2 + (size_t)l * FF * DD, WTh + base + (size_t)3*DD*DD + (size_t)DD*FF,
                                         WTl + base + (size_t)3*DD*DD + (size_t)DD*FF, FF, DD, 1, 0, 0, 0);
    }
    tsplit(projw, WTh + PROJ_OFF, WTl + PROJ_OFF, DD, VV, 1, 0, 0, 0);

    // ---- embed --------------------------------------------------------------
    {
        int total = NROWS * (DD / 4);
        embed_k<<<(total + 255) / 256, 256>>>(tokens, emb, pos, X);
    }

    for (int l = 0; l < LL; l++) {
        size_t base = (size_t)l * LYR_BLK;
        const __half* qkvTh = WTh + base;
        const __half* w1Th  = WTh + base + (size_t)3 * DD * DD;
        const __half* w2Th  = WTh + base + (size_t)3 * DD * DD + (size_t)DD * FF;
        const float* b1_l = b1 + (size_t)l * FF;
        const float* b2_l = b2 + (size_t)l * DD;

        // h = ln1(x)  (split only)
        ln_k<<<NROWS, 256>>>(X, Hf, Hh, Hl, g1 + (size_t)l * DD, bln1 + (size_t)l * DD, 0);

        // q,k,v = h @ W   [2-term wide]: V fp32 (z=2); Q,K h+l (for 3-term QK)
        gemm2(Hh, Hl, qkvTh, QKVf, QKVh, QKVl, NROWS, DD, DD, 1.f,
              nullptr, nullptr, 0, /*cf*/4, /*ch*/3, /*cl*/3, 3,
              0, (long)DD * DD, ND, 0);

        // VT split (h+l; V is B-role in 3-term AV)
        tsplit(QKVf + 2 * ND, VTh, VTl, TT, DD, BB, (long)TT * DD, (long)DD * TT, 1);

        // s = (q @ k^T) * scale   [3-term; causal tile-skip]
        gemm3(QKVh, QKVl, QKVh + ND, QKVl + ND, S, TT, TT, DD, scale,
              nullptr, 1, BB, (long)TT * DD, (long)TT * DD, (long)TT * TT, 0);

        // causal softmax -> split S
        {
            dim3 grid(TT, BB);
            softmax_k<<<grid, 256>>>(S, Sh, Sl);
        }

        // x = s @ v + x   [3-term; causal K-limit]
        gemm3(Sh, Sl, VTh, VTl, X, TT, DD, TT, 1.f,
              X, 2, BB, (long)TT * TT, (long)DD * TT, (long)TT * DD, (long)TT * DD);

        // y = ln2(x)  (fp32 needed as w2 addm)
        ln_k<<<NROWS, 256>>>(X, Hf, Hh, Hl, g2 + (size_t)l * DD, bln2 + (size_t)l * DD, 1);

        // ff = relu(y @ w1 + b1)  [2-term wide; split out]
        gemm2(Hh, Hl, w1Th, nullptr, Fh, Fl, NROWS, FF, DD, 1.f,
              b1_l, nullptr, 1, 0, 1, 1, 1, 0, 0, 0, 0);

        // x = ff @ w2 + b2 + y  [2-term wide; fp32 + (last layer) split]
        int lm = (l == LL - 1) ? 1 : 0;
        gemm2(Fh, Fl, w2Th, X, Xh, Xl, NROWS, DD, FF, 1.f,
              b2_l, Hf, 0, 1, lm, lm, 1, 0, 0, 0, 0);
    }

    // logits = x @ proj_w + proj_b  [2-term wide]
    gemm2(Xh, Xl, WTh + PROJ_OFF, out, nullptr, nullptr,
          NROWS, VV, DD, 1.f, projb, nullptr, 0, 1, 0, 0, 1,
          0, 0, 0, 0);
}

// round 16
// speedup vs baseline: 1.5341x; 1.0993x over previous
#include <cuda_runtime.h>
#include <cuda_fp16.h>
#include <math.h>
#include <stdint.h>

#define BB 2
#define TT 2048
#define DD 1024
#define LL 4
#define VV 32000
#define FF (4*DD)
#define NROWS (BB*TT)   // 4096

// WT scratch layout (elements): per layer: WqT,WkT,WvT (DD*DD each), w1T (DD*FF), w2T (FF*DD)
#define LYR_BLK (3*DD*DD + DD*FF + FF*DD)
#define PROJ_OFF ((size_t)LL*LYR_BLK)
#define WT_TOTAL (PROJ_OFF + (size_t)DD*VV)

// ---------------- scratch (device globals; no allocations allowed) ----------
__device__ float g_X[(size_t)NROWS*DD];
__device__ float g_Hf[(size_t)NROWS*DD];
__device__ float g_QKVf[(size_t)3*NROWS*DD];
__device__ float g_S[(size_t)BB*TT*TT];
__device__ __half g_Hh[(size_t)NROWS*DD],   g_Hl[(size_t)NROWS*DD];
__device__ __half g_Xh[(size_t)NROWS*DD],   g_Xl[(size_t)NROWS*DD];
__device__ __half g_QKVh[(size_t)3*NROWS*DD], g_QKVl[(size_t)3*NROWS*DD];
__device__ __half g_Sh[(size_t)BB*TT*TT],   g_Sl[(size_t)BB*TT*TT];
__device__ __half g_Fh[(size_t)NROWS*FF],   g_Fl[(size_t)NROWS*FF];
__device__ __half g_WTh[WT_TOTAL],          g_WTl[WT_TOTAL];
__device__ __half g_VTh[(size_t)BB*DD*TT],  g_VTl[(size_t)BB*DD*TT];

// ============================ helpers ========================================
__device__ __forceinline__ uint32_t smem_u32(const void* p) {
    uint32_t a;
    asm("{ .reg .u64 t; cvta.to.shared.u64 t, %1; cvt.u32.u64 %0, t; }" : "=r"(a) : "l"(p));
    return a;
}
// 64B-row swizzle: XOR byte bits [4:6) with bits [7:9)
#define SWZ64(o) ((o) ^ (((o) >> 3) & 0x30))

__device__ __forceinline__ void ldm_x4(uint32_t* r, uint32_t addr) {
    asm volatile("ldmatrix.sync.aligned.m8n8.x4.shared.b16 {%0,%1,%2,%3}, [%4];"
                 : "=r"(r[0]), "=r"(r[1]), "=r"(r[2]), "=r"(r[3]) : "r"(addr));
}
__device__ __forceinline__ void mma_f16(float* d, const uint32_t* a, uint32_t b0, uint32_t b1) {
    asm volatile(
        "mma.sync.aligned.m16n8k16.row.col.f32.f16.f16.f32 "
        "{%0,%1,%2,%3}, {%4,%5,%6,%7}, {%8,%9}, {%0,%1,%2,%3};"
        : "+f"(d[0]), "+f"(d[1]), "+f"(d[2]), "+f"(d[3])
        : "r"(a[0]), "r"(a[1]), "r"(a[2]), "r"(a[3]), "r"(b0), "r"(b1));
}
__device__ __forceinline__ void cpa16(uint32_t dst, const void* src) {
    asm volatile("cp.async.cg.shared.global [%0], [%1], 16;" :: "r"(dst), "l"(src));
}
#define CP_COMMIT() asm volatile("cp.async.commit_group;" ::: "memory")
#define CP_WAIT2()  asm volatile("cp.async.wait_group 2;" ::: "memory")

__device__ __forceinline__ uint32_t pk2(__half a, __half b) {
    __half2 t = __halves2half2(a, b);
    return *reinterpret_cast<uint32_t*>(&t);
}

#define STG_SZ 32768
#define NSTG 4
#define SHM_TOTAL (NSTG*STG_SZ)
#define BK 32

// =============== wide GEMM: tile 128(M) x 256(N), A-terms templated =========
// AT=2: C = alpha*(Ah+Al)@Bh^T ; AT=1: C = alpha*Ah@Bh^T. (+bias)(+relu)(+addm)
// A:[M][K] f16 hi(/lo), B:[N][K] f16.
// Stage (32KB): Ah @0 (8K), Al @8192, Bh @16384 (16K, 256 rows x 32 f16).
template<int AT>
__global__ __launch_bounds__(256) void gemm2w_k(
    const __half* __restrict__ Ahp, const __half* __restrict__ Alp,
    const __half* __restrict__ Bhp,
    float* __restrict__ Cf,
    __half* __restrict__ Ch, __half* __restrict__ Cl,
    int M, int N, int K, float alpha,
    const float* __restrict__ bias,
    const float* __restrict__ addm,
    int relu, int cfMask, int chMask, int clMask,
    long sA, long sB, long sC, long sAdd)
{
    extern __shared__ char smem[];
    const uint32_t smb = smem_u32(smem);
    const int tid = threadIdx.x;
    const long z = blockIdx.z;

    Ahp += z * sA; if (AT == 2) Alp += z * sA;
    Bhp += z * sB;
    const bool wCf = Cf && ((cfMask >> z) & 1);
    const bool wCh = Ch && ((chMask >> z) & 1);
    const bool wCl = Cl && ((clMask >> z) & 1);
    if (Cf) Cf += z * sC;
    if (Ch) Ch += z * sC;
    if (Cl) Cl += z * sC;
    if (addm) addm += z * sAdd;

    const int rowBlk = blockIdx.y * 128;
    const int colBlk = blockIdx.x * 256;
    const int nCh = K / BK;

    const int lr = tid >> 1, half = tid & 1;
    const __half* pa_h = Ahp + (long)(rowBlk + lr) * K + half * 16;
    const __half* pa_l = (AT == 2) ? (Alp + (long)(rowBlk + lr) * K + half * 16) : nullptr;
    const __half* pb   = Bhp + (long)(colBlk + tid) * K;
    const uint32_t oA0 = SWZ64((uint32_t)(lr * 64 + half * 32));
    const uint32_t oA1 = SWZ64((uint32_t)(lr * 64 + half * 32 + 16));
    const uint32_t oB0 = SWZ64((uint32_t)(tid * 64));
    const uint32_t oB1 = SWZ64((uint32_t)(tid * 64 + 16));
    const uint32_t oB2 = SWZ64((uint32_t)(tid * 64 + 32));
    const uint32_t oB3 = SWZ64((uint32_t)(tid * 64 + 48));

    // prologue: issue first NSTG-1 = 3 chunks
#pragma unroll
    for (int s = 0; s < NSTG - 1; s++) {
        if (s < nCh) {
            uint32_t sb = smb + (uint32_t)s * STG_SZ;
            long k0 = (long)s * BK;
            cpa16(sb + oA0,         pa_h + k0);  cpa16(sb + oA1,         pa_h + k0 + 8);
            if (AT == 2) {
                cpa16(sb + 8192 + oA0, pa_l + k0);  cpa16(sb + 8192 + oA1, pa_l + k0 + 8);
            }
            cpa16(sb + 16384 + oB0, pb + k0);      cpa16(sb + 16384 + oB1, pb + k0 + 8);
            cpa16(sb + 16384 + oB2, pb + k0 + 16); cpa16(sb + 16384 + oB3, pb + k0 + 24);
        }
        CP_COMMIT();
    }

    float acc[4][8][4];
#pragma unroll
    for (int i = 0; i < 4; i++)
#pragma unroll
        for (int j = 0; j < 8; j++)
#pragma unroll
            for (int k = 0; k < 4; k++) acc[i][j][k] = 0.f;

    const int w = tid >> 5, lane = tid & 31;
    const int wm = (w & 1) * 64;
    const int wn = (w >> 1) * 64;

    for (int c = 0; c < nCh; c++) {
        CP_WAIT2();
        __syncthreads();
        const uint32_t sb = smb + (uint32_t)(c & (NSTG - 1)) * STG_SZ;
#pragma unroll
        for (int ks = 0; ks < 2; ks++) {
            uint32_t bh[8][2];
#pragma unroll
            for (int nt2 = 0; nt2 < 4; nt2++) {
                uint32_t off = SWZ64((uint32_t)((wn + nt2 * 16 + ((lane >> 4) & 1) * 8 + (lane & 7)) * 64
                                                + ks * 32 + ((lane >> 3) & 1) * 16));
                uint32_t r[4];
                ldm_x4(r, sb + 16384 + off);
                bh[nt2 * 2][0] = r[0]; bh[nt2 * 2][1] = r[1];
                bh[nt2 * 2 + 1][0] = r[2]; bh[nt2 * 2 + 1][1] = r[3];
            }
#pragma unroll
            for (int mt = 0; mt < 4; mt++) {
                uint32_t off = SWZ64((uint32_t)((wm + mt * 16 + (lane & 15)) * 64
                                                + ks * 32 + (lane >> 4) * 16));
                uint32_t ah4[4], al4[4];
                ldm_x4(ah4, sb + off);
                if (AT == 2) ldm_x4(al4, sb + 8192 + off);
#pragma unroll
                for (int nt = 0; nt < 8; nt++) mma_f16(acc[mt][nt], ah4, bh[nt][0], bh[nt][1]);
                if (AT == 2) {
#pragma unroll
                    for (int nt = 0; nt < 8; nt++) mma_f16(acc[mt][nt], al4, bh[nt][0], bh[nt][1]);
                }
            }
        }
        if (c + NSTG - 1 < nCh) {
            uint32_t sbn = smb + (uint32_t)((c + NSTG - 1) & (NSTG - 1)) * STG_SZ;
            long k0 = (long)(c + NSTG - 1) * BK;
            cpa16(sbn + oA0,         pa_h + k0);  cpa16(sbn + oA1,         pa_h + k0 + 8);
            if (AT == 2) {
                cpa16(sbn + 8192 + oA0, pa_l + k0);  cpa16(sbn + 8192 + oA1, pa_l + k0 + 8);
            }
            cpa16(sbn + 16384 + oB0, pb + k0);      cpa16(sbn + 16384 + oB1, pb + k0 + 8);
            cpa16(sbn + 16384 + oB2, pb + k0 + 16); cpa16(sbn + 16384 + oB3, pb + k0 + 24);
        }
        CP_COMMIT();
    }

    // ---- epilogue ----
#pragma unroll
    for (int mt = 0; mt < 4; mt++) {
        int r0 = rowBlk + wm + mt * 16 + (lane >> 2);
#pragma unroll
        for (int nt = 0; nt < 8; nt++) {
            int cc = colBlk + wn + nt * 8 + (lane & 3) * 2;
            float2 v0, v1;
            v0.x = acc[mt][nt][0] * alpha; v0.y = acc[mt][nt][1] * alpha;
            v1.x = acc[mt][nt][2] * alpha; v1.y = acc[mt][nt][3] * alpha;
            if (bias) {
                float2 bb = *reinterpret_cast<const float2*>(bias + cc);
                v0.x += bb.x; v0.y += bb.y; v1.x += bb.x; v1.y += bb.y;
            }
            if (relu) {
                v0.x = fmaxf(v0.x, 0.f); v0.y = fmaxf(v0.y, 0.f);
                v1.x = fmaxf(v1.x, 0.f); v1.y = fmaxf(v1.y, 0.f);
            }
            if (addm) {
                float2 a0 = *reinterpret_cast<const float2*>(addm + (long)r0 * N + cc);
                float2 a1 = *reinterpret_cast<const float2*>(addm + (long)(r0 + 8) * N + cc);
                v0.x += a0.x; v0.y += a0.y; v1.x += a1.x; v1.y += a1.y;
            }
            if (wCf) {
                *reinterpret_cast<float2*>(Cf + (long)r0 * N + cc) = v0;
                *reinterpret_cast<float2*>(Cf + (long)(r0 + 8) * N + cc) = v1;
            }
            if (wCh || wCl) {
                __half h0 = __float2half_rn(v0.x), h1 = __float2half_rn(v0.y);
                __half h2 = __float2half_rn(v1.x), h3 = __float2half_rn(v1.y);
                if (wCh) {
                    *reinterpret_cast<uint32_t*>(Ch + (long)r0 * N + cc)       = pk2(h0, h1);
                    *reinterpret_cast<uint32_t*>(Ch + (long)(r0 + 8) * N + cc) = pk2(h2, h3);
                }
                if (wCl) {
                    *reinterpret_cast<uint32_t*>(Cl + (long)r0 * N + cc) =
                        pk2(__float2half_rn(v0.x - __half2float(h0)),
                            __float2half_rn(v0.y - __half2float(h1)));
                    *reinterpret_cast<uint32_t*>(Cl + (long)(r0 + 8) * N + cc) =
                        pk2(__float2half_rn(v1.x - __half2float(h2)),
                            __float2half_rn(v1.y - __half2float(h3)));
                }
            }
        }
    }
}

// =============== 3-term GEMM: tile 128x128 (QK^T and A·V) ====================
// C = alpha*(Ah+Al)@(Bh+Bl)^T. cmode: 1 = causal tile-skip, 2 = causal K-limit.
__global__ __launch_bounds__(256) void gemm3_k(
    const __half* __restrict__ Ahp, const __half* __restrict__ Alp,
    const __half* __restrict__ Bhp, const __half* __restrict__ Blp,
    float* __restrict__ Cf,
    int M, int N, int K, float alpha,
    const float* __restrict__ addm,
    int cmode,
    long sA, long sB, long sC, long sAdd)
{
    extern __shared__ char smem[];
    const uint32_t smb = smem_u32(smem);
    const int tid = threadIdx.x;
    const long z = blockIdx.z;

    Ahp += z * sA; Alp += z * sA;
    Bhp += z * sB; Blp += z * sB;
    Cf += z * sC;
    if (addm) addm += z * sAdd;

    const int rowBlk = blockIdx.y * 128;
    const int colBlk = blockIdx.x * 128;
    if (cmode == 1 && colBlk >= rowBlk + 128) return;

    int kMax = K;
    if (cmode == 2) { kMax = rowBlk + 128; if (kMax > K) kMax = K; }
    const int nCh = kMax / BK;

    const int lr = tid >> 1, half = tid & 1;
    const __half* pa_h = Ahp + (long)(rowBlk + lr) * K + half * 16;
    const __half* pa_l = Alp + (long)(rowBlk + lr) * K + half * 16;
    const __half* pb_h = Bhp + (long)(colBlk + lr) * K + half * 16;
    const __half* pb_l = Blp + (long)(colBlk + lr) * K + half * 16;
    const uint32_t o0 = SWZ64((uint32_t)(lr * 64 + half * 32));
    const uint32_t o1 = SWZ64((uint32_t)(lr * 64 + half * 32 + 16));

#pragma unroll
    for (int s = 0; s < NSTG - 1; s++) {
        if (s < nCh) {
            uint32_t sb = smb + (uint32_t)s * STG_SZ;
            long k0 = (long)s * BK;
            cpa16(sb + o0,         pa_h + k0);  cpa16(sb + o1,         pa_h + k0 + 8);
            cpa16(sb + 8192  + o0, pa_l + k0);  cpa16(sb + 8192  + o1, pa_l + k0 + 8);
            cpa16(sb + 16384 + o0, pb_h + k0);  cpa16(sb + 16384 + o1, pb_h + k0 + 8);
            cpa16(sb + 24576 + o0, pb_l + k0);  cpa16(sb + 24576 + o1, pb_l + k0 + 8);
        }
        CP_COMMIT();
    }

    float acc[4][4][4];
#pragma unroll
    for (int i = 0; i < 4; i++)
#pragma unroll
        for (int j = 0; j < 4; j++)
#pragma unroll
            for (int k = 0; k < 4; k++) acc[i][j][k] = 0.f;

    const int w = tid >> 5, lane = tid & 31;
    const int wm = (w & 1) * 64;
    const int wn = (w >> 1) * 32;

    for (int c = 0; c < nCh; c++) {
        CP_WAIT2();
        __syncthreads();
        const uint32_t sb = smb + (uint32_t)(c & (NSTG - 1)) * STG_SZ;
#pragma unroll
        for (int ks = 0; ks < 2; ks++) {
            uint32_t ah[4][4], al[4][4];
#pragma unroll
            for (int mt = 0; mt < 4; mt++) {
                uint32_t off = SWZ64((uint32_t)((wm + mt * 16 + (lane & 15)) * 64
                                                + ks * 32 + (lane >> 4) * 16));
                ldm_x4(ah[mt], sb + off);
                ldm_x4(al[mt], sb + 8192 + off);
            }
            uint32_t bh[4][2], bl[4][2];
#pragma unroll
            for (int nt2 = 0; nt2 < 2; nt2++) {
                uint32_t off = SWZ64((uint32_t)((wn + nt2 * 16 + ((lane >> 4) & 1) * 8 + (lane & 7)) * 64
                                                + ks * 32 + ((lane >> 3) & 1) * 16));
                uint32_t r[4];
                ldm_x4(r, sb + 16384 + off);
                bh[nt2 * 2][0] = r[0]; bh[nt2 * 2][1] = r[1];
                bh[nt2 * 2 + 1][0] = r[2]; bh[nt2 * 2 + 1][1] = r[3];
                ldm_x4(r, sb + 24576 + off);
                bl[nt2 * 2][0] = r[0]; bl[nt2 * 2][1] = r[1];
                bl[nt2 * 2 + 1][0] = r[2]; bl[nt2 * 2 + 1][1] = r[3];
            }
#pragma unroll
            for (int mt = 0; mt < 4; mt++)
#pragma unroll
                for (int nt = 0; nt < 4; nt++) {
                    mma_f16(acc[mt][nt], ah[mt], bh[nt][0], bh[nt][1]);
                    mma_f16(acc[mt][nt], ah[mt], bl[nt][0], bl[nt][1]);
                    mma_f16(acc[mt][nt], al[mt], bh[nt][0], bh[nt][1]);
                }
        }
        if (c + NSTG - 1 < nCh) {
            uint32_t sbn = smb + (uint32_t)((c + NSTG - 1) & (NSTG - 1)) * STG_SZ;
            long k0 = (long)(c + NSTG - 1) * BK;
            cpa16(sbn + o0,         pa_h + k0);  cpa16(sbn + o1,         pa_h + k0 + 8);
            cpa16(sbn + 8192  + o0, pa_l + k0);  cpa16(sbn + 8192  + o1, pa_l + k0 + 8);
            cpa16(sbn + 16384 + o0, pb_h + k0);  cpa16(sbn + 16384 + o1, pb_h + k0 + 8);
            cpa16(sbn + 24576 + o0, pb_l + k0);  cpa16(sbn + 24576 + o1, pb_l + k0 + 8);
        }
        CP_COMMIT();
    }

#pragma unroll
    for (int mt = 0; mt < 4; mt++) {
        int r0 = rowBlk + wm + mt * 16 + (lane >> 2);
#pragma unroll
        for (int nt = 0; nt < 4; nt++) {
            int cc = colBlk + wn + nt * 8 + (lane & 3) * 2;
            float2 v0, v1;
            v0.x = acc[mt][nt][0] * alpha; v0.y = acc[mt][nt][1] * alpha;
            v1.x = acc[mt][nt][2] * alpha; v1.y = acc[mt][nt][3] * alpha;
            if (addm) {
                float2 a0 = *reinterpret_cast<const float2*>(addm + (long)r0 * N + cc);
                float2 a1 = *reinterpret_cast<const float2*>(addm + (long)(r0 + 8) * N + cc);
                v0.x += a0.x; v0.y += a0.y; v1.x += a1.x; v1.y += a1.y;
            }
            *reinterpret_cast<float2*>(Cf + (long)r0 * N + cc) = v0;
            *reinterpret_cast<float2*>(Cf + (long)(r0 + 8) * N + cc) = v1;
        }
    }
}

// ---------------- transpose + f16 split: W[R][C] -> T[C][R] hi(/lo) ---------
__global__ void tsplit_k(const float* __restrict__ W,
                         __half* __restrict__ Th, __half* __restrict__ Tl,
                         int R, int C, long sIn, long sOut, int writeL)
{
    __shared__ float t[32][33];
    W  += (long)blockIdx.z * sIn;
    Th += (long)blockIdx.z * sOut;
    Tl += (long)blockIdx.z * sOut;
    int c0 = blockIdx.x * 32, r0 = blockIdx.y * 32;
    int tx = threadIdx.x, ty = threadIdx.y;
#pragma unroll
    for (int j = 0; j < 32; j += 8)
        t[ty + j][tx] = W[(long)(r0 + ty + j) * C + c0 + tx];
    __syncthreads();
#pragma unroll
    for (int j = 0; j < 32; j += 8) {
        int oc = c0 + ty + j;
        float v = t[tx][ty + j];
        __half h = __float2half_rn(v);
        Th[(long)oc * R + r0 + tx] = h;
        if (writeL)
            Tl[(long)oc * R + r0 + tx] = __float2half_rn(v - __half2float(h));
    }
}

// ---------------- embed: x = emb[tok] + pos ---------------------------------
__global__ void embed_k(const int* __restrict__ tok,
                        const float* __restrict__ emb,
                        const float* __restrict__ pos,
                        float* __restrict__ X)
{
    int idx = blockIdx.x * blockDim.x + threadIdx.x;
    int total = NROWS * (DD / 4);
    if (idx >= total) return;
    int d4 = idx % (DD / 4);
    int bt = idx / (DD / 4);
    int t = bt % TT;
    int token = tok[bt];
    float4 e = reinterpret_cast<const float4*>(emb + (size_t)token * DD)[d4];
    float4 p = reinterpret_cast<const float4*>(pos + (size_t)t * DD)[d4];
    float4 o; o.x = e.x + p.x; o.y = e.y + p.y; o.z = e.z + p.z; o.w = e.w + p.w;
    reinterpret_cast<float4*>(X + (size_t)bt * DD)[d4] = o;
}

// ---------------- layernorm: fp32 in -> (opt fp32) + f16-split out ----------
__global__ void ln_k(const float* __restrict__ X,
                     float* __restrict__ Yf,
                     __half* __restrict__ Yh, __half* __restrict__ Yl,
                     const float* __restrict__ g, const float* __restrict__ b,
                     int writeF)
{
    int row = blockIdx.x;
    int tid = threadIdx.x;
    const float4* x4 = reinterpret_cast<const float4*>(X + (size_t)row * DD);
    float4 v = x4[tid];
    __shared__ float sh[256];

    float s = v.x + v.y + v.z + v.w;
    sh[tid] = s; __syncthreads();
    for (int o = 128; o > 0; o >>= 1) { if (tid < o) sh[tid] += sh[tid + o]; __syncthreads(); }
    float mu = sh[0] * (1.0f / DD);
    __syncthreads();

    float c0 = v.x - mu, c1 = v.y - mu, c2 = v.z - mu, c3 = v.w - mu;
    sh[tid] = c0 * c0 + c1 * c1 + c2 * c2 + c3 * c3; __syncthreads();
    for (int o = 128; o > 0; o >>= 1) { if (tid < o) sh[tid] += sh[tid + o]; __syncthreads(); }
    float inv = rsqrtf(sh[0] * (1.0f / DD) + 1e-5f);

    float4 gv = reinterpret_cast<const float4*>(g)[tid];
    float4 bv = reinterpret_cast<const float4*>(b)[tid];
    float4 o4;
    o4.x = c0 * inv * gv.x + bv.x;
    o4.y = c1 * inv * gv.y + bv.y;
    o4.z = c2 * inv * gv.z + bv.z;
    o4.w = c3 * inv * gv.w + bv.w;
    if (writeF)
        reinterpret_cast<float4*>(Yf + (size_t)row * DD)[tid] = o4;

    __half h0 = __float2half_rn(o4.x), h1 = __float2half_rn(o4.y);
    __half h2 = __float2half_rn(o4.z), h3 = __float2half_rn(o4.w);
    uint2 hv, lv;
    hv.x = pk2(h0, h1); hv.y = pk2(h2, h3);
    lv.x = pk2(__float2half_rn(o4.x - __half2float(h0)),
               __float2half_rn(o4.y - __half2float(h1)));
    lv.y = pk2(__float2half_rn(o4.z - __half2float(h2)),
               __float2half_rn(o4.w - __half2float(h3)));
    *reinterpret_cast<uint2*>(Yh + (size_t)row * DD + tid * 4) = hv;
    *reinterpret_cast<uint2*>(Yl + (size_t)row * DD + tid * 4) = lv;
}

// ---------------- causal softmax: fp32 S -> f16-split out -------------------
__global__ void softmax_k(const float* __restrict__ S,
                          __half* __restrict__ Sh, __half* __restrict__ Sl)
{
    int t = blockIdx.x, b = blockIdx.y;
    int tid = threadIdx.x;
    const float* row = S + ((size_t)b * TT + t) * TT;
    __half* rh = Sh + ((size_t)b * TT + t) * TT;
    __half* rl = Sl + ((size_t)b * TT + t) * TT;
    __shared__ float ex[TT];
    __shared__ float sh[256];

    float mx = -1e30f;
    for (int c = tid; c <= t; c += 256) { float v = row[c]; ex[c] = v; mx = fmaxf(mx, v); }
    sh[tid] = mx; __syncthreads();
    for (int o = 128; o > 0; o >>= 1) { if (tid < o) sh[tid] = fmaxf(sh[tid], sh[tid + o]); __syncthreads(); }
    mx = sh[0]; __syncthreads();

    float sum = 0.f;
    for (int c = tid; c <= t; c += 256) { float e = __expf(ex[c] - mx); ex[c] = e; sum += e; }
    sh[tid] = sum; __syncthreads();
    for (int o = 128; o > 0; o >>= 1) { if (tid < o) sh[tid] += sh[tid + o]; __syncthreads(); }
    float inv = 1.0f / sh[0];

    for (int c = tid; c < TT; c += 256) {
        float p = (c <= t) ? ex[c] * inv : 0.0f;
        __half h = __float2half_rn(p);
        rh[c] = h;
        rl[c] = __float2half_rn(p - __half2float(h));
    }
}

// ---------------- host-side dispatch -----------------------------------------
static void gemm2(int at,
                  const __half* Ah, const __half* Al, const __half* Bh,
                  float* Cf, __half* Ch, __half* Cl,
                  int M, int N, int K, float alpha,
                  const float* bias, const float* addm, int relu,
                  int cfMask, int chMask, int clMask, int batch,
                  long sA, long sB, long sC, long sAdd)
{
    dim3 grid(N / 256, M / 128, batch), blk(256);
    if (at == 1)
        gemm2w_k<1><<<grid, blk, SHM_TOTAL>>>(Ah, Al, Bh, Cf, Ch, Cl,
                                              M, N, K, alpha, bias, addm, relu,
                                              cfMask, chMask, clMask, sA, sB, sC, sAdd);
    else
        gemm2w_k<2><<<grid, blk, SHM_TOTAL>>>(Ah, Al, Bh, Cf, Ch, Cl,
                                              M, N, K, alpha, bias, addm, relu,
                                              cfMask, chMask, clMask, sA, sB, sC, sAdd);
}

static void gemm3(const __half* Ah, const __half* Al,
                  const __half* Bh, const __half* Bl,
                  float* Cf, int M, int N, int K, float alpha,
                  const float* addm, int cmode, int batch,
                  long sA, long sB, long sC, long sAdd)
{
    dim3 grid(N / 128, M / 128, batch), blk(256);
    gemm3_k<<<grid, blk, SHM_TOTAL>>>(Ah, Al, Bh, Bl, Cf,
                                      M, N, K, alpha, addm, cmode,
                                      sA, sB, sC, sAdd);
}

static void tsplit(const float* W, __half* Th, __half* Tl,
                   int R, int C, int batch, long sIn, long sOut, int writeL)
{
    dim3 g(C / 32, R / 32, batch), b(32, 8);
    tsplit_k<<<g, b>>>(W, Th, Tl, R, C, sIn, sOut, writeL);
}

extern "C" void kernel_launch(void* const* d_in, const int* in_sizes, int n_in,
                              void* d_out, int out_size)
{
    const int*   tokens = (const int*)  d_in[0];
    const float* emb    = (const float*)d_in[1];
    const float* pos    = (const float*)d_in[2];
    const float* Wq     = (const float*)d_in[3];
    const float* Wk     = (const float*)d_in[4];
    const float* Wv     = (const float*)d_in[5];
    const float* w1     = (const float*)d_in[6];
    const float* b1     = (const float*)d_in[7];
    const float* w2     = (const float*)d_in[8];
    const float* b2     = (const float*)d_in[9];
    const float* g1     = (const float*)d_in[10];
    const float* bln1   = (const float*)d_in[11];
    const float* g2     = (const float*)d_in[12];
    const float* bln2   = (const float*)d_in[13];
    const float* projw  = (const float*)d_in[14];
    const float* projb  = (const float*)d_in[15];
    float* out = (float*)d_out;

    cudaFuncSetAttribute(gemm2w_k<1>, cudaFuncAttributeMaxDynamicSharedMemorySize, SHM_TOTAL);
    cudaFuncSetAttribute(gemm2w_k<2>, cudaFuncAttributeMaxDynamicSharedMemorySize, SHM_TOTAL);
    cudaFuncSetAttribute(gemm3_k,     cudaFuncAttributeMaxDynamicSharedMemorySize, SHM_TOTAL);

    float *X, *Hf, *QKVf, *S;
    __half *Hh, *Hl, *Xh, *Xl, *QKVh, *QKVl, *Sh, *Sl, *Fh, *Fl, *WTh, *WTl, *VTh, *VTl;
    cudaGetSymbolAddress((void**)&X,    g_X);
    cudaGetSymbolAddress((void**)&Hf,   g_Hf);
    cudaGetSymbolAddress((void**)&QKVf, g_QKVf);
    cudaGetSymbolAddress((void**)&S,    g_S);
    cudaGetSymbolAddress((void**)&Hh,   g_Hh);   cudaGetSymbolAddress((void**)&Hl,   g_Hl);
    cudaGetSymbolAddress((void**)&Xh,   g_Xh);   cudaGetSymbolAddress((void**)&Xl,   g_Xl);
    cudaGetSymbolAddress((void**)&QKVh, g_QKVh); cudaGetSymbolAddress((void**)&QKVl, g_QKVl);
    cudaGetSymbolAddress((void**)&Sh,   g_Sh);   cudaGetSymbolAddress((void**)&Sl,   g_Sl);
    cudaGetSymbolAddress((void**)&Fh,   g_Fh);   cudaGetSymbolAddress((void**)&Fl,   g_Fl);
    cudaGetSymbolAddress((void**)&WTh,  g_WTh);  cudaGetSymbolAddress((void**)&WTl,  g_WTl);
    cudaGetSymbolAddress((void**)&VTh,  g_VTh);  cudaGetSymbolAddress((void**)&VTl,  g_VTl);

    const float scale = 0.03125f;   // 1/sqrt(1024)
    const long ND = (long)NROWS * DD;

    // ---- weight prepass: transpose + f16 (hi only; weights are B-role) ------
    for (int l = 0; l < LL; l++) {
        size_t base = (size_t)l * LYR_BLK;
        tsplit(Wq + (size_t)l * DD * DD, WTh + base,                   WTl + base,                   DD, DD, 1, 0, 0, 0);
        tsplit(Wk + (size_t)l * DD * DD, WTh + base + (size_t)DD*DD,   WTl + base + (size_t)DD*DD,   DD, DD, 1, 0, 0, 0);
        tsplit(Wv + (size_t)l * DD * DD, WTh + base + (size_t)2*DD*DD, WTl + base + (size_t)2*DD*DD, DD, DD, 1, 0, 0, 0);
        tsplit(w1 + (size_t)l * DD * FF, WTh + base + (size_t)3*DD*DD, WTl + base + (size_t)3*DD*DD, DD, FF, 1, 0, 0, 0);
        tsplit(w2 + (size_t)l * FF * DD, WTh + base + (size_t)3*DD*DD + (size_t)DD*FF,
                                         WTl + base + (size_t)3*DD*DD + (size_t)DD*FF, FF, DD, 1, 0, 0, 0);
    }
    tsplit(projw, WTh + PROJ_OFF, WTl + PROJ_OFF, DD, VV, 1, 0, 0, 0);

    // ---- embed --------------------------------------------------------------
    {
        int total = NROWS * (DD / 4);
        embed_k<<<(total + 255) / 256, 256>>>(tokens, emb, pos, X);
    }

    for (int l = 0; l < LL; l++) {
        size_t base = (size_t)l * LYR_BLK;
        const __half* qkvTh = WTh + base;
        const __half* w1Th  = WTh + base + (size_t)3 * DD * DD;
        const __half* w2Th  = WTh + base + (size_t)3 * DD * DD + (size_t)DD * FF;
        const float* b1_l = b1 + (size_t)l * FF;
        const float* b2_l = b2 + (size_t)l * DD;

        // h = ln1(x)  (split only)
        ln_k<<<NROWS, 256>>>(X, Hf, Hh, Hl, g1 + (size_t)l * DD, bln1 + (size_t)l * DD, 0);

        // q,k,v = h @ W   [2-term wide]: V fp32 (z=2); Q,K h+l (for 3-term QK)
        gemm2(2, Hh, Hl, qkvTh, QKVf, QKVh, QKVl, NROWS, DD, DD, 1.f,
              nullptr, nullptr, 0, /*cf*/4, /*ch*/3, /*cl*/3, 3,
              0, (long)DD * DD, ND, 0);

        // VT split (h+l; V is B-role in 3-term AV)
        tsplit(QKVf + 2 * ND, VTh, VTl, TT, DD, BB, (long)TT * DD, (long)DD * TT, 1);

        // s = (q @ k^T) * scale   [3-term; causal tile-skip]
        gemm3(QKVh, QKVl, QKVh + ND, QKVl + ND, S, TT, TT, DD, scale,
              nullptr, 1, BB, (long)TT * DD, (long)TT * DD, (long)TT * TT, 0);

        // causal softmax -> split S
        {
            dim3 grid(TT, BB);
            softmax_k<<<grid, 256>>>(S, Sh, Sl);
        }

        // x = s @ v + x   [3-term; causal K-limit]
        gemm3(Sh, Sl, VTh, VTl, X, TT, DD, TT, 1.f,
              X, 2, BB, (long)TT * TT, (long)DD * TT, (long)TT * DD, (long)TT * DD);

        // y = ln2(x)  (fp32 needed as w2 addm)
        ln_k<<<NROWS, 256>>>(X, Hf, Hh, Hl, g2 + (size_t)l * DD, bln2 + (size_t)l * DD, 1);

        // ff = relu(y @ w1 + b1)  [2-term wide; split out]
        gemm2(2, Hh, Hl, w1Th, nullptr, Fh, Fl, NROWS, FF, DD, 1.f,
              b1_l, nullptr, 1, 0, 1, 1, 1, 0, 0, 0, 0);

        // x = ff @ w2 + b2 + y  [2-term wide; fp32 + (last layer) Xh only]
        int lm = (l == LL - 1) ? 1 : 0;
        gemm2(2, Fh, Fl, w2Th, X, Xh, Xl, NROWS, DD, FF, 1.f,
              b2_l, Hf, 0, 1, lm, 0, 1, 0, 0, 0, 0);
    }

    // logits = x @ proj_w + proj_b  [1-term wide: Xh @ Wh]
    gemm2(1, Xh, nullptr, WTh + PROJ_OFF, out, nullptr, nullptr,
          NROWS, VV, DD, 1.f, projb, nullptr, 0, 1, 0, 0, 1,
          0, 0, 0, 0);
}